// round 13
// baseline (speedup 1.0000x reference)
#include <cuda_runtime.h>
#include <cuda_fp16.h>
#include <cstdint>

#define M_TOK 8192
#define DMODEL 768
#define DINNER 1536
#define CONVD  1792
#define NH     24
#define HD     64
#define DST    128
#define NPROJ  3352
#define NPAD   3456
#define LSEQ   2048

// ---------------- device scratch (no allocation allowed) ----------------
__device__ float g_zx[M_TOK * NPROJ];    // in_proj output (z | xBC | dt-unused)
__device__ float g_xc[M_TOK * CONVD];    // conv+silu output (xh | B | C)
__device__ float2 g_dtdA[96 * LSEQ];     // packed (dt, dA) per (b*NH+h, l)
__device__ float g_y [M_TOK * DINNER];   // scan output + D skip
__device__ float g_cstate[96 * 3 * 64 * 128];  // final local state, chunks 0..2
__device__ float g_pref[96 * LSEQ];            // per-chunk dA prefix products

__device__ __half g_Xh[M_TOK * DMODEL];
__device__ __half g_Wih[NPAD * DMODEL];
__device__ __half g_Yh[M_TOK * DINNER];
__device__ __half g_Woh[DMODEL * DINNER];

typedef unsigned long long ull;

__device__ __forceinline__ uint32_t smem_u32(const void* p) {
    uint32_t a;
    asm("{ .reg .u64 t; cvta.to.shared.u64 t, %1; cvt.u32.u64 %0, t; }"
        : "=r"(a) : "l"(p));
    return a;
}

__device__ __forceinline__ void cp16(uint32_t dst, const void* src) {
    asm volatile("cp.async.cg.shared.global [%0], [%1], 16;"
                 :: "r"(dst), "l"(src) : "memory");
}
__device__ __forceinline__ void cp8(uint32_t dst, const void* src) {
    asm volatile("cp.async.ca.shared.global [%0], [%1], 8;"
                 :: "r"(dst), "l"(src) : "memory");
}
__device__ __forceinline__ void cp4(uint32_t dst, const void* src) {
    asm volatile("cp.async.ca.shared.global [%0], [%1], 4;"
                 :: "r"(dst), "l"(src) : "memory");
}
__device__ __forceinline__ void cp_commit() {
    asm volatile("cp.async.commit_group;" ::: "memory");
}
__device__ __forceinline__ void cp_wait0() {
    asm volatile("cp.async.wait_group 0;" ::: "memory");
}
__device__ __forceinline__ void cp_wait1() {
    asm volatile("cp.async.wait_group 1;" ::: "memory");
}
__device__ __forceinline__ void cp_wait2() {
    asm volatile("cp.async.wait_group 2;" ::: "memory");
}

__device__ __forceinline__ void ldmx4(uint32_t* r, uint32_t addr) {
    asm volatile("ldmatrix.sync.aligned.m8n8.x4.shared.b16 {%0,%1,%2,%3}, [%4];"
                 : "=r"(r[0]), "=r"(r[1]), "=r"(r[2]), "=r"(r[3]) : "r"(addr));
}

__device__ __forceinline__ void mma16816h(float* c, const uint32_t* a, const uint32_t* b) {
    asm volatile(
        "mma.sync.aligned.m16n8k16.row.col.f32.f16.f16.f32 "
        "{%0,%1,%2,%3}, {%4,%5,%6,%7}, {%8,%9}, {%0,%1,%2,%3};"
        : "+f"(c[0]), "+f"(c[1]), "+f"(c[2]), "+f"(c[3])
        : "r"(a[0]), "r"(a[1]), "r"(a[2]), "r"(a[3]), "r"(b[0]), "r"(b[1]));
}

// ---------------------------------------------------------------------------
// fp16 1-pass GEMM (NT): C = fp16(A) * fp16(B)^T, fp32 accumulate.
// CTA tile 256x128, 8 warps (warp tile 64x64), K-chunk 64, 2-stage ring.
// ---------------------------------------------------------------------------
#define BK      64
#define LDT_B   144
#define ROW_A   256
#define ROW_BT  128
#define STAGE_B ((ROW_A + ROW_BT) * LDT_B)   // 55296

__global__ __launch_bounds__(256, 1)
void mma_gemm(const __half* __restrict__ Ah_, const __half* __restrict__ Bh_,
              const float* __restrict__ R, float* __restrict__ C,
              int Nact, int K)
{
    extern __shared__ char smem[];
    uint32_t sb = smem_u32(smem);
    int tid  = threadIdx.x;
    int wid  = tid >> 5, lane = tid & 31;
    int wm   = wid & 3, wn = wid >> 2;
    int m0   = blockIdx.y * 256, n0 = blockIdx.x * 128;

    const size_t rowK = (size_t)K * 2;

    auto load_stage = [&](int s, int k0) {
        uint32_t d0 = sb + s * STAGE_B;
#pragma unroll
        for (int i = 0; i < 12; i++) {
            int idx = tid + i * 256;
            int row = idx >> 3, ch = idx & 7;
            const char* src;
            if (row < ROW_A)
                src = (const char*)Ah_ + (size_t)(m0 + row) * rowK + k0 * 2;
            else
                src = (const char*)Bh_ + (size_t)(n0 + row - ROW_A) * rowK + k0 * 2;
            cp16(d0 + row * LDT_B + ch * 16, src + ch * 16);
        }
        cp_commit();
    };

    float acc[4][8][4];
#pragma unroll
    for (int mt = 0; mt < 4; mt++)
#pragma unroll
        for (int nt = 0; nt < 8; nt++)
#pragma unroll
            for (int j = 0; j < 4; j++) acc[mt][nt][j] = 0.f;

    int nch = K / BK;
    load_stage(0, 0);

    int a_row = wm * 64 + (lane & 7) + ((lane >> 3) & 1) * 8;
    int a_cb  = ((lane >> 4) & 1) * 16;
    int b_row = wn * 64 + ((lane >> 4) & 1) * 8 + (lane & 7);
    int b_cb  = ((lane >> 3) & 1) * 16;

    for (int c = 0; c < nch; c++) {
        if (c + 1 < nch) { load_stage((c + 1) & 1, (c + 1) * BK); cp_wait1(); }
        else             { cp_wait0(); }
        __syncthreads();

        uint32_t st = sb + (c & 1) * STAGE_B;
        uint32_t Ah = st;
        uint32_t Bh = st + ROW_A * LDT_B;

#pragma unroll
        for (int kk = 0; kk < 4; kk++) {
            int kb = kk * 32;
            uint32_t ah[4][4];
#pragma unroll
            for (int mt = 0; mt < 4; mt++) {
                uint32_t off = (uint32_t)((a_row + mt * 16) * LDT_B + kb + a_cb);
                ldmx4(ah[mt], Ah + off);
            }
            uint32_t bh[8][2];
#pragma unroll
            for (int q = 0; q < 4; q++) {
                uint32_t off = (uint32_t)((b_row + q * 16) * LDT_B + kb + b_cb);
                uint32_t r[4];
                ldmx4(r, Bh + off);
                bh[2*q][0] = r[0]; bh[2*q][1] = r[1];
                bh[2*q+1][0] = r[2]; bh[2*q+1][1] = r[3];
            }
#pragma unroll
            for (int mt = 0; mt < 4; mt++)
#pragma unroll
                for (int nt = 0; nt < 8; nt++)
                    mma16816h(acc[mt][nt], ah[mt], bh[nt]);
        }
        __syncthreads();
    }

    int l4 = lane >> 2, l2 = (lane & 3) * 2;
#pragma unroll
    for (int mt = 0; mt < 4; mt++) {
        int gm = m0 + wm * 64 + mt * 16 + l4;
#pragma unroll
        for (int nt = 0; nt < 8; nt++) {
            int gn = n0 + wn * 64 + nt * 8 + l2;
            if (gn < Nact) {
                size_t o0 = (size_t)gm * Nact + gn;
                size_t o1 = (size_t)(gm + 8) * Nact + gn;
                float2 v0 = make_float2(acc[mt][nt][0], acc[mt][nt][1]);
                float2 v1 = make_float2(acc[mt][nt][2], acc[mt][nt][3]);
                if (R) {
                    const float2 r0 = *(const float2*)&R[o0];
                    const float2 r1 = *(const float2*)&R[o1];
                    v0.x += r0.x; v0.y += r0.y; v1.x += r1.x; v1.y += r1.y;
                }
                *(float2*)&C[o0] = v0;
                *(float2*)&C[o1] = v1;
            }
        }
    }
}

// ---------------------------------------------------------------------------
// fp32 -> fp16 convert (float4-vectorized, zero-padded)
// ---------------------------------------------------------------------------
__global__ void conv_hi16(const float* __restrict__ w, __half* __restrict__ hi,
                          int nsrc4, int ntot4)
{
    int i = blockIdx.x * blockDim.x + threadIdx.x;
    if (i >= ntot4) return;
    float4 v = make_float4(0.f, 0.f, 0.f, 0.f);
    if (i < nsrc4) v = ((const float4*)w)[i];
    __half2 h0 = __floats2half2_rn(v.x, v.y);
    __half2 h1 = __floats2half2_rn(v.z, v.w);
    ((uint2*)hi)[i] = make_uint2(*(uint32_t*)&h0, *(uint32_t*)&h1);
}

// ---------------------------------------------------------------------------
__device__ __forceinline__ ull pk2(float x, float y) {
    ull r; asm("mov.b64 %0,{%1,%2};" : "=l"(r) : "f"(x), "f"(y)); return r;
}
__device__ __forceinline__ float2 upk2(ull v) {
    float2 r; asm("mov.b64 {%0,%1},%2;" : "=f"(r.x), "=f"(r.y) : "l"(v)); return r;
}
__device__ __forceinline__ ull f2fma(ull a, ull b, ull c) {
    ull d; asm("fma.rn.f32x2 %0,%1,%2,%3;" : "=l"(d) : "l"(a), "l"(b), "l"(c)); return d;
}
__device__ __forceinline__ ull f2mul(ull a, ull b) {
    ull d; asm("mul.rn.f32x2 %0,%1,%2;" : "=l"(d) : "l"(a), "l"(b)); return d;
}

// ---------------------------------------------------------------------------
// Causal depthwise conv1d + SiLU, float4 over 4 channels
// ---------------------------------------------------------------------------
__global__ void conv_silu(const float* __restrict__ cw, const float* __restrict__ cb)
{
    int idx = blockIdx.x * blockDim.x + threadIdx.x;
    if (idx >= M_TOK * (CONVD / 4)) return;
    int c4 = idx % (CONVD / 4), m = idx / (CONVD / 4);
    int c = c4 * 4;
    int l = m & (LSEQ - 1);
    float4 acc = *(const float4*)&cb[c];
    float4 w0 = ((const float4*)cw)[c];
    float4 w1 = ((const float4*)cw)[c + 1];
    float4 w2 = ((const float4*)cw)[c + 2];
    float4 w3 = ((const float4*)cw)[c + 3];
    const float* wk0 = (const float*)&w0;
    const float* wk1 = (const float*)&w1;
    const float* wk2 = (const float*)&w2;
    const float* wk3 = (const float*)&w3;
#pragma unroll
    for (int k = 0; k < 4; k++) {
        int ll = l - 3 + k;
        if (ll >= 0) {
            float4 xv = *(const float4*)&g_zx[(size_t)(m - 3 + k) * NPROJ + DINNER + c];
            acc.x = fmaf(xv.x, wk0[k], acc.x);
            acc.y = fmaf(xv.y, wk1[k], acc.y);
            acc.z = fmaf(xv.z, wk2[k], acc.z);
            acc.w = fmaf(xv.w, wk3[k], acc.w);
        }
    }
    acc.x *= 1.f / (1.f + __expf(-acc.x));
    acc.y *= 1.f / (1.f + __expf(-acc.y));
    acc.z *= 1.f / (1.f + __expf(-acc.z));
    acc.w *= 1.f / (1.f + __expf(-acc.w));
    *(float4*)&g_xc[(size_t)m * CONVD + c] = acc;
}

// ---------------------------------------------------------------------------
// EXACT fp32 dt path (dt errors amplify exponentially in the scan).
// ---------------------------------------------------------------------------
__global__ __launch_bounds__(256)
void dt_exact(const float* __restrict__ x, const float* __restrict__ wi,
              const float* __restrict__ dtb, const float* __restrict__ alog)
{
    __shared__ __align__(16) float xrow[DMODEL];
    int m = blockIdx.x;
    int tid = threadIdx.x;
    if (tid < 192)
        ((float4*)xrow)[tid] = ((const float4*)(x + (size_t)m * DMODEL))[tid];
    __syncthreads();
    int w = tid >> 5, lane = tid & 31;
#pragma unroll
    for (int hh = 0; hh < 3; hh++) {
        int h = w + hh * 8;
        const float4* wr4 = (const float4*)(wi + (size_t)(DINNER + CONVD + h) * DMODEL);
        const float4* xr4 = (const float4*)xrow;
        float dot = 0.f;
#pragma unroll
        for (int j = 0; j < 6; j++) {
            int k = lane + j * 32;
            float4 a = xr4[k], b = wr4[k];
            dot = fmaf(a.x, b.x, fmaf(a.y, b.y, fmaf(a.z, b.z, fmaf(a.w, b.w, dot))));
        }
#pragma unroll
        for (int o = 16; o > 0; o >>= 1) dot += __shfl_xor_sync(0xffffffffu, dot, o);
        if (lane == 0) {
            float v = dot + dtb[h];
            float sp = fmaxf(v, 0.f) + log1pf(expf(-fabsf(v)));
            float A = -expf(alog[h]);
            int b = m / LSEQ, l = m % LSEQ;
            g_dtdA[(size_t)(b * NH + h) * LSEQ + l] = make_float2(sp, expf(sp * A));
        }
    }
}

// ---------------------------------------------------------------------------
// Chunked selective SSM scan: 4 chunks of 512, 3 CTAs/SM co-residency.
// ---------------------------------------------------------------------------
#define NSTG 16
#define STGF 336
#define LCH  512

__global__ __launch_bounds__(256, 3)
void scan_kernel(const float* __restrict__ Dv)
{
    __shared__ __align__(16) float sh[NSTG][STGF];
    __shared__ __align__(16) float yb[8][1024];
    uint32_t sb = smem_u32(sh);
    int bc = blockIdx.x;
    int bh = bc % 96;
    int c  = bc / 96;                  // 0..3
    int t0 = c * LCH;
    const int T = LCH;
    int b = bh / NH, h = bh % NH;
    int tid = threadIdx.x;
    int pg = tid >> 4, nq = tid & 15;
    int xorm = (pg & 1) * 16;
    float dh0 = (nq == 0) ? Dv[h] : 0.f;

    const char* src = nullptr;
    uint32_t dsto = 0;
    size_t stride = (size_t)CONVD * 4;
    const char* xcb = (const char*)(g_xc + ((size_t)b * LSEQ + t0) * CONVD);
    if (tid < 16) {
        src = xcb + (size_t)h * HD * 4 + tid * 16;
        dsto = tid * 16;
    } else if (tid < 48) {
        int t = tid - 16;
        src = xcb + (size_t)DINNER * 4 + t * 16;
        dsto = 256 + (uint32_t)((((t & 1) * 16) + (t >> 1)) * 16);
    } else if (tid < 80) {
        int t = tid - 48;
        src = xcb + (size_t)(DINNER + DST) * 4 + t * 16;
        dsto = 768 + (uint32_t)((((t & 1) * 16) + (t >> 1)) * 16);
    } else if (tid == 80) {
        src = (const char*)(g_dtdA + (size_t)bh * LSEQ + t0);
        dsto = 1280;
        stride = 8;
    }

    auto issue_group = [&](int gq) {
#pragma unroll
        for (int q = 0; q < 4; q++) {
            int step = 4 * gq + q;
            if (step < T && tid <= 80) {
                uint32_t d = sb + (uint32_t)((step & (NSTG - 1)) * (STGF * 4)) + dsto;
                if (tid < 80) cp16(d, src); else cp8(d, src);
                src += stride;
            }
        }
        cp_commit();
    };

    issue_group(0); issue_group(1); issue_group(2);

    ull st[4][4];
#pragma unroll
    for (int pi = 0; pi < 4; pi++)
#pragma unroll
        for (int k = 0; k < 4; k++) st[pi][k] = 0ull;

    float* ybase = g_y + ((size_t)b * LSEQ + t0) * DINNER + h * HD;
    float run = 1.f;
    float* prefp = g_pref + (size_t)bh * LSEQ + t0;

    for (int g = 0; g < T / 4; g++) {
        cp_wait2();
        __syncthreads();
        issue_group(g + 3);

#pragma unroll
        for (int q = 0; q < 4; q++) {
            int l = 4 * g + q;
            const float* bp = sh[l & (NSTG - 1)];
            float4 xv = *(const float4*)(bp + 4 * pg);
            float2 da = *(const float2*)(bp + 320);
            ull dA2 = pk2(da.y, da.y);
            float xs[4] = {xv.x, xv.y, xv.z, xv.w};
            ull dtx2[4];
#pragma unroll
            for (int pi = 0; pi < 4; pi++) {
                float d = da.x * xs[pi];
                dtx2[pi] = pk2(d, d);
            }
            const ulonglong2* B4 = (const ulonglong2*)(bp + 64);
            const ulonglong2* C4 = (const ulonglong2*)(bp + 192);
            ull bb[4], cc[4];
#pragma unroll
            for (int j = 0; j < 2; j++) {
                ulonglong2 bv = B4[j * 16 + nq];
                ulonglong2 cv = C4[j * 16 + nq];
                bb[2*j] = bv.x; bb[2*j+1] = bv.y;
                cc[2*j] = cv.x; cc[2*j+1] = cv.y;
            }
            float* yrow = yb[l & 7] + 64 * pg;
#pragma unroll
            for (int pi = 0; pi < 4; pi++) {
                ull acc2 = 0ull;
#pragma unroll
                for (int k = 0; k < 4; k++) {
                    st[pi][k] = f2fma(st[pi][k], dA2, f2mul(dtx2[pi], bb[k]));
                    acc2 = f2fma(st[pi][k], cc[k], acc2);
                }
                float2 av = upk2(acc2);
                yrow[(16 * pi + nq) ^ xorm] = fmaf(dh0, xs[pi], av.x + av.y);
            }
            if (tid == 255 && c > 0) {
                run *= da.y;
                prefp[l] = run;
            }
        }

        if (g & 1) {
            __syncthreads();
#pragma unroll
            for (int k = 0; k < 2; k++) {
                int o = tid + 256 * k;
                int s_ = o >> 6, p = o & 63;
                int rpg = p >> 2, rpi = p & 3;
                const float4* r4 = (const float4*)(yb[s_] + 64 * rpg
                                                   + (16 * (rpi ^ (rpg & 1))));
                float4 v0 = r4[0], v1 = r4[1], v2 = r4[2], v3 = r4[3];
                float acc = (((v0.x + v0.y) + (v0.z + v0.w))
                           + ((v1.x + v1.y) + (v1.z + v1.w)))
                          + (((v2.x + v2.y) + (v2.z + v2.w))
                           + ((v3.x + v3.y) + (v3.z + v3.w)));
                int l0 = 4 * (g - 1);
                ybase[(size_t)(l0 + s_) * DINNER + p] = acc;
            }
        }
    }

    // store final local state for chunks 0..2 (fixup input; layout [p][n])
    if (c < 3) {
        float* cs = g_cstate + ((size_t)bh * 3 + c) * 8192;
#pragma unroll
        for (int pi = 0; pi < 4; pi++) {
            int p = 4 * pg + pi;
#pragma unroll
            for (int j = 0; j < 2; j++) {
                float2 a = upk2(st[pi][2*j]);
                float2 d = upk2(st[pi][2*j+1]);
                float4 v = make_float4(a.x, a.y, d.x, d.y);
                *(float4*)(cs + p * 128 + 8 * nq + 4 * j) = v;
            }
        }
    }
}

// ---------------------------------------------------------------------------
// Fix-up: y[t] += pref_t * (C_t . S_init_c), chunks 1..3, each in 2 halves.
// S_init_c = Sl_{c-1} + Q_{c-1} * S_init_{c-1}  (recurrence over stored states)
// ---------------------------------------------------------------------------
#define FSTG 16
#define FSTGF 132

__global__ __launch_bounds__(512, 2)
void fixup_kernel()
{
    __shared__ __align__(16) float sh[FSTG][FSTGF];
    __shared__ __align__(16) float yb[8][512];
    uint32_t sb = smem_u32(sh);
    int bx = blockIdx.x;
    int bh = bx % 96;
    int r  = bx / 96;                 // 0..5
    int c  = 1 + (r >> 1);            // chunk 1..3
    int half = r & 1;
    const int Th = LCH / 2;           // 256
    int t0 = c * LCH + half * Th;
    int b = bh / NH, h = bh % NH;
    int tid = threadIdx.x;
    int p = tid >> 3, nb = tid & 7;

    // S_init_c via recurrence over stored local states
    ull sini[8];
    {
        float4 a4[4];
        const float4* s0 = (const float4*)(g_cstate + ((size_t)bh * 3) * 8192
                                           + p * 128 + nb * 16);
#pragma unroll
        for (int i = 0; i < 4; i++) a4[i] = s0[i];
        for (int k = 1; k < c; k++) {
            float Qk = g_pref[(size_t)bh * LSEQ + k * LCH + (LCH - 1)];
            const float4* sk = (const float4*)(g_cstate + ((size_t)bh * 3 + k) * 8192
                                               + p * 128 + nb * 16);
#pragma unroll
            for (int i = 0; i < 4; i++) {
                float4 v = sk[i];
                a4[i].x = fmaf(Qk, a4[i].x, v.x);
                a4[i].y = fmaf(Qk, a4[i].y, v.y);
                a4[i].z = fmaf(Qk, a4[i].z, v.z);
                a4[i].w = fmaf(Qk, a4[i].w, v.w);
            }
        }
#pragma unroll
        for (int i = 0; i < 4; i++) {
            sini[2*i]   = pk2(a4[i].x, a4[i].y);
            sini[2*i+1] = pk2(a4[i].z, a4[i].w);
        }
    }

    const char* src = nullptr;
    uint32_t dsto = 0;
    size_t stride = (size_t)CONVD * 4;
    if (tid < 32) {
        src = (const char*)(g_xc + ((size_t)b * LSEQ + t0) * CONVD + DINNER + DST) + tid * 16;
        dsto = (uint32_t)((((tid & 3) * 8) + (tid >> 2)) * 16);
    } else if (tid == 32) {
        src = (const char*)(g_pref + (size_t)bh * LSEQ + t0);
        dsto = 512;
        stride = 4;
    }

    auto issue_group = [&](int gq) {
#pragma unroll
        for (int q = 0; q < 4; q++) {
            int step = 4 * gq + q;
            if (step < Th && tid <= 32) {
                uint32_t d = sb + (uint32_t)((step & (FSTG - 1)) * (FSTGF * 4)) + dsto;
                if (tid < 32) cp16(d, src); else cp4(d, src);
                src += stride;
            }
        }
        cp_commit();
    };
    issue_group(0); issue_group(1); issue_group(2);

    float* ybase = g_y + ((size_t)b * LSEQ + t0) * DINNER + h * HD;
    int rs = tid >> 6, rp = tid & 63;

    for (int g = 0; g < Th / 4; g++) {
        cp_wait2();
        __syncthreads();
        issue_group(g + 3);

#pragma unroll
        for (int q = 0; q < 4; q++) {
            int l = 4 * g + q;
            const float* bp = sh[l & (FSTG - 1)];
            const ulonglong2* C4 = (const ulonglong2*)bp;
            ull cc[8];
#pragma unroll
            for (int j = 0; j < 4; j++) {
                ulonglong2 cv = C4[j * 8 + nb];
                cc[2*j] = cv.x; cc[2*j+1] = cv.y;
            }
            ull acc2 = 0ull;
#pragma unroll
            for (int i = 0; i < 8; i++) acc2 = f2fma(sini[i], cc[i], acc2);
            float2 av = upk2(acc2);
            yb[l & 7][tid] = (av.x + av.y) * bp[128];
        }

        if (g & 1) {
            __syncthreads();
            const float4* r4 = (const float4*)(yb[rs] + rp * 8);
            float4 v0 = r4[0], v1 = r4[1];
            float acc = ((v0.x + v0.y) + (v0.z + v0.w))
                      + ((v1.x + v1.y) + (v1.z + v1.w));
            int l0 = 4 * (g - 1);
            float* yp = ybase + (size_t)(l0 + rs) * DINNER + rp;
            *yp += acc;
        }
    }
}

// ---------------------------------------------------------------------------
// gate + rmsnorm, emits fp16
// ---------------------------------------------------------------------------
__global__ __launch_bounds__(384)
void gate_norm(const float* __restrict__ nw)
{
    __shared__ float warpsum[12];
    __shared__ float stot;
    int m = blockIdx.x;
    int tid = threadIdx.x;
    float4 yv = ((const float4*)(g_y + (size_t)m * DINNER))[tid];
    float4 zv = ((const float4*)(g_zx + (size_t)m * NPROJ))[tid];
    float4 v;
    v.x = yv.x * (zv.x / (1.f + __expf(-zv.x)));
    v.y = yv.y * (zv.y / (1.f + __expf(-zv.y)));
    v.z = yv.z * (zv.z / (1.f + __expf(-zv.z)));
    v.w = yv.w * (zv.w / (1.f + __expf(-zv.w)));
    float ss = fmaf(v.x, v.x, fmaf(v.y, v.y, fmaf(v.z, v.z, v.w * v.w)));
#pragma unroll
    for (int o = 16; o > 0; o >>= 1) ss += __shfl_xor_sync(0xffffffffu, ss, o);
    if ((tid & 31) == 0) warpsum[tid >> 5] = ss;
    __syncthreads();
    if (tid == 0) {
        float t = 0.f;
#pragma unroll
        for (int w = 0; w < 12; w++) t += warpsum[w];
        stot = t;
    }
    __syncthreads();
    float scale = rsqrtf(stot / (float)DINNER + 1e-5f);
    float4 nv = ((const float4*)nw)[tid];
    v.x *= scale * nv.x; v.y *= scale * nv.y;
    v.z *= scale * nv.z; v.w *= scale * nv.w;
    __half2 h0 = __floats2half2_rn(v.x, v.y);
    __half2 h1 = __floats2half2_rn(v.z, v.w);
    ((uint2*)(g_Yh + (size_t)m * DINNER))[tid] =
        make_uint2(*(uint32_t*)&h0, *(uint32_t*)&h1);
}

// ---------------------------------------------------------------------------
extern "C" void kernel_launch(void* const* d_in, const int* in_sizes, int n_in,
                              void* d_out, int out_size)
{
    const float* x    = (const float*)d_in[0];
    const float* wi   = (const float*)d_in[1];
    const float* cw   = (const float*)d_in[2];
    const float* cb   = (const float*)d_in[3];
    const float* dtb  = (const float*)d_in[4];
    const float* alog = (const float*)d_in[5];
    const float* Dv   = (const float*)d_in[6];
    const float* nw   = (const float*)d_in[7];
    const float* wo   = (const float*)d_in[8];
    float* out = (float*)d_out;

    float *zx;
    __half *xh, *wih, *yh, *woh;
    cudaGetSymbolAddress((void**)&zx,  g_zx);
    cudaGetSymbolAddress((void**)&xh,  g_Xh);
    cudaGetSymbolAddress((void**)&wih, g_Wih);
    cudaGetSymbolAddress((void**)&yh,  g_Yh);
    cudaGetSymbolAddress((void**)&woh, g_Woh);

    static const int smem_bytes = 2 * STAGE_B;  // 110592 B
    cudaFuncSetAttribute(mma_gemm, cudaFuncAttributeMaxDynamicSharedMemorySize, smem_bytes);

    dim3 blk(256);

    conv_hi16<<<(M_TOK * DMODEL / 4 + 255) / 256, blk>>>(x, xh,
                                                         M_TOK * DMODEL / 4, M_TOK * DMODEL / 4);
    conv_hi16<<<(NPAD * DMODEL / 4 + 255) / 256, blk>>>(wi, wih,
                                                        NPROJ * DMODEL / 4, NPAD * DMODEL / 4);
    conv_hi16<<<(DMODEL * DINNER / 4 + 255) / 256, blk>>>(wo, woh,
                                                          DMODEL * DINNER / 4, DMODEL * DINNER / 4);

    // in_proj (fp16 1-pass; dt recomputed exactly below)
    mma_gemm<<<dim3(NPAD / 128, M_TOK / 256), blk, smem_bytes>>>(
        xh, wih, nullptr, zx, NPROJ, DMODEL);

    dt_exact<<<M_TOK, blk>>>(x, wi, dtb, alog);
    conv_silu<<<(M_TOK * (CONVD / 4) + 255) / 256, blk>>>(cw, cb);
    scan_kernel<<<384, 256>>>(Dv);
    fixup_kernel<<<576, 512>>>();
    gate_norm<<<M_TOK, 384>>>(nw);

    // out_proj + residual (fp16 1-pass)
    mma_gemm<<<dim3(DMODEL / 128, M_TOK / 256), blk, smem_bytes>>>(
        yh, woh, x, out, DMODEL, DINNER);
}

// round 14
// speedup vs baseline: 1.0244x; 1.0244x over previous
#include <cuda_runtime.h>
#include <cuda_fp16.h>
#include <cstdint>

#define M_TOK 8192
#define DMODEL 768
#define DINNER 1536
#define CONVD  1792
#define NH     24
#define HD     64
#define DST    128
#define NPROJ  3352
#define NPAD   3456
#define LSEQ   2048

// ---------------- device scratch (no allocation allowed) ----------------
__device__ float g_zx[M_TOK * NPROJ];    // in_proj output (z | xBC | dt-unused)
__device__ float g_xc[M_TOK * CONVD];    // conv+silu output (xh | B | C)
__device__ float2 g_dtdA[96 * LSEQ];     // packed (dt, dA) per (b*NH+h, l)
__device__ float g_y [M_TOK * DINNER];   // scan output + D skip
__device__ float g_cstate[96 * 2 * 64 * 128];  // per-chunk final local state
__device__ float g_pref[96 * LSEQ];            // per-chunk dA prefix products

__device__ __half g_Xh[M_TOK * DMODEL];
__device__ __half g_Wih[NPAD * DMODEL];
__device__ __half g_Yh[M_TOK * DINNER];
__device__ __half g_Woh[DMODEL * DINNER];

typedef unsigned long long ull;

__device__ __forceinline__ uint32_t smem_u32(const void* p) {
    uint32_t a;
    asm("{ .reg .u64 t; cvta.to.shared.u64 t, %1; cvt.u32.u64 %0, t; }"
        : "=r"(a) : "l"(p));
    return a;
}

__device__ __forceinline__ void cp16(uint32_t dst, const void* src) {
    asm volatile("cp.async.cg.shared.global [%0], [%1], 16;"
                 :: "r"(dst), "l"(src) : "memory");
}
__device__ __forceinline__ void cp8(uint32_t dst, const void* src) {
    asm volatile("cp.async.ca.shared.global [%0], [%1], 8;"
                 :: "r"(dst), "l"(src) : "memory");
}
__device__ __forceinline__ void cp4(uint32_t dst, const void* src) {
    asm volatile("cp.async.ca.shared.global [%0], [%1], 4;"
                 :: "r"(dst), "l"(src) : "memory");
}
__device__ __forceinline__ void cp_commit() {
    asm volatile("cp.async.commit_group;" ::: "memory");
}
__device__ __forceinline__ void cp_wait0() {
    asm volatile("cp.async.wait_group 0;" ::: "memory");
}
__device__ __forceinline__ void cp_wait1() {
    asm volatile("cp.async.wait_group 1;" ::: "memory");
}
__device__ __forceinline__ void cp_wait2() {
    asm volatile("cp.async.wait_group 2;" ::: "memory");
}

__device__ __forceinline__ void ldmx4(uint32_t* r, uint32_t addr) {
    asm volatile("ldmatrix.sync.aligned.m8n8.x4.shared.b16 {%0,%1,%2,%3}, [%4];"
                 : "=r"(r[0]), "=r"(r[1]), "=r"(r[2]), "=r"(r[3]) : "r"(addr));
}

__device__ __forceinline__ void mma16816h(float* c, const uint32_t* a, const uint32_t* b) {
    asm volatile(
        "mma.sync.aligned.m16n8k16.row.col.f32.f16.f16.f32 "
        "{%0,%1,%2,%3}, {%4,%5,%6,%7}, {%8,%9}, {%0,%1,%2,%3};"
        : "+f"(c[0]), "+f"(c[1]), "+f"(c[2]), "+f"(c[3])
        : "r"(a[0]), "r"(a[1]), "r"(a[2]), "r"(a[3]), "r"(b[0]), "r"(b[1]));
}

// ---------------------------------------------------------------------------
// fp16 1-pass GEMM (NT): C = fp16(A) * fp16(B)^T, fp32 accumulate.
// CTA tile 256x128, 8 warps (warp tile 64x64), K-chunk 64, 2-stage ring.
// ---------------------------------------------------------------------------
#define BK      64
#define LDT_B   144
#define ROW_A   256
#define ROW_BT  128
#define STAGE_B ((ROW_A + ROW_BT) * LDT_B)   // 55296

__global__ __launch_bounds__(256, 1)
void mma_gemm(const __half* __restrict__ Ah_, const __half* __restrict__ Bh_,
              const float* __restrict__ R, float* __restrict__ C,
              int Nact, int K)
{
    extern __shared__ char smem[];
    uint32_t sb = smem_u32(smem);
    int tid  = threadIdx.x;
    int wid  = tid >> 5, lane = tid & 31;
    int wm   = wid & 3, wn = wid >> 2;
    int m0   = blockIdx.y * 256, n0 = blockIdx.x * 128;

    const size_t rowK = (size_t)K * 2;

    auto load_stage = [&](int s, int k0) {
        uint32_t d0 = sb + s * STAGE_B;
#pragma unroll
        for (int i = 0; i < 12; i++) {
            int idx = tid + i * 256;
            int row = idx >> 3, ch = idx & 7;
            const char* src;
            if (row < ROW_A)
                src = (const char*)Ah_ + (size_t)(m0 + row) * rowK + k0 * 2;
            else
                src = (const char*)Bh_ + (size_t)(n0 + row - ROW_A) * rowK + k0 * 2;
            cp16(d0 + row * LDT_B + ch * 16, src + ch * 16);
        }
        cp_commit();
    };

    float acc[4][8][4];
#pragma unroll
    for (int mt = 0; mt < 4; mt++)
#pragma unroll
        for (int nt = 0; nt < 8; nt++)
#pragma unroll
            for (int j = 0; j < 4; j++) acc[mt][nt][j] = 0.f;

    int nch = K / BK;
    load_stage(0, 0);

    int a_row = wm * 64 + (lane & 7) + ((lane >> 3) & 1) * 8;
    int a_cb  = ((lane >> 4) & 1) * 16;
    int b_row = wn * 64 + ((lane >> 4) & 1) * 8 + (lane & 7);
    int b_cb  = ((lane >> 3) & 1) * 16;

    for (int c = 0; c < nch; c++) {
        if (c + 1 < nch) { load_stage((c + 1) & 1, (c + 1) * BK); cp_wait1(); }
        else             { cp_wait0(); }
        __syncthreads();

        uint32_t st = sb + (c & 1) * STAGE_B;
        uint32_t Ah = st;
        uint32_t Bh = st + ROW_A * LDT_B;

#pragma unroll
        for (int kk = 0; kk < 4; kk++) {
            int kb = kk * 32;
            uint32_t ah[4][4];
#pragma unroll
            for (int mt = 0; mt < 4; mt++) {
                uint32_t off = (uint32_t)((a_row + mt * 16) * LDT_B + kb + a_cb);
                ldmx4(ah[mt], Ah + off);
            }
            uint32_t bh[8][2];
#pragma unroll
            for (int q = 0; q < 4; q++) {
                uint32_t off = (uint32_t)((b_row + q * 16) * LDT_B + kb + b_cb);
                uint32_t r[4];
                ldmx4(r, Bh + off);
                bh[2*q][0] = r[0]; bh[2*q][1] = r[1];
                bh[2*q+1][0] = r[2]; bh[2*q+1][1] = r[3];
            }
#pragma unroll
            for (int mt = 0; mt < 4; mt++)
#pragma unroll
                for (int nt = 0; nt < 8; nt++)
                    mma16816h(acc[mt][nt], ah[mt], bh[nt]);
        }
        __syncthreads();
    }

    int l4 = lane >> 2, l2 = (lane & 3) * 2;
#pragma unroll
    for (int mt = 0; mt < 4; mt++) {
        int gm = m0 + wm * 64 + mt * 16 + l4;
#pragma unroll
        for (int nt = 0; nt < 8; nt++) {
            int gn = n0 + wn * 64 + nt * 8 + l2;
            if (gn < Nact) {
                size_t o0 = (size_t)gm * Nact + gn;
                size_t o1 = (size_t)(gm + 8) * Nact + gn;
                float2 v0 = make_float2(acc[mt][nt][0], acc[mt][nt][1]);
                float2 v1 = make_float2(acc[mt][nt][2], acc[mt][nt][3]);
                if (R) {
                    const float2 r0 = *(const float2*)&R[o0];
                    const float2 r1 = *(const float2*)&R[o1];
                    v0.x += r0.x; v0.y += r0.y; v1.x += r1.x; v1.y += r1.y;
                }
                *(float2*)&C[o0] = v0;
                *(float2*)&C[o1] = v1;
            }
        }
    }
}

// ---------------------------------------------------------------------------
// fp32 -> fp16 convert (float4-vectorized, zero-padded)
// ---------------------------------------------------------------------------
__global__ void conv_hi16(const float* __restrict__ w, __half* __restrict__ hi,
                          int nsrc4, int ntot4)
{
    int i = blockIdx.x * blockDim.x + threadIdx.x;
    if (i >= ntot4) return;
    float4 v = make_float4(0.f, 0.f, 0.f, 0.f);
    if (i < nsrc4) v = ((const float4*)w)[i];
    __half2 h0 = __floats2half2_rn(v.x, v.y);
    __half2 h1 = __floats2half2_rn(v.z, v.w);
    ((uint2*)hi)[i] = make_uint2(*(uint32_t*)&h0, *(uint32_t*)&h1);
}

// ---------------------------------------------------------------------------
__device__ __forceinline__ ull pk2(float x, float y) {
    ull r; asm("mov.b64 %0,{%1,%2};" : "=l"(r) : "f"(x), "f"(y)); return r;
}
__device__ __forceinline__ float2 upk2(ull v) {
    float2 r; asm("mov.b64 {%0,%1},%2;" : "=f"(r.x), "=f"(r.y) : "l"(v)); return r;
}
__device__ __forceinline__ ull f2fma(ull a, ull b, ull c) {
    ull d; asm("fma.rn.f32x2 %0,%1,%2,%3;" : "=l"(d) : "l"(a), "l"(b), "l"(c)); return d;
}
__device__ __forceinline__ ull f2mul(ull a, ull b) {
    ull d; asm("mul.rn.f32x2 %0,%1,%2;" : "=l"(d) : "l"(a), "l"(b)); return d;
}

// ---------------------------------------------------------------------------
// Causal depthwise conv1d + SiLU, float4 over 4 channels
// ---------------------------------------------------------------------------
__global__ void conv_silu(const float* __restrict__ cw, const float* __restrict__ cb)
{
    int idx = blockIdx.x * blockDim.x + threadIdx.x;
    if (idx >= M_TOK * (CONVD / 4)) return;
    int c4 = idx % (CONVD / 4), m = idx / (CONVD / 4);
    int c = c4 * 4;
    int l = m & (LSEQ - 1);
    float4 acc = *(const float4*)&cb[c];
    float4 w0 = ((const float4*)cw)[c];
    float4 w1 = ((const float4*)cw)[c + 1];
    float4 w2 = ((const float4*)cw)[c + 2];
    float4 w3 = ((const float4*)cw)[c + 3];
    const float* wk0 = (const float*)&w0;
    const float* wk1 = (const float*)&w1;
    const float* wk2 = (const float*)&w2;
    const float* wk3 = (const float*)&w3;
#pragma unroll
    for (int k = 0; k < 4; k++) {
        int ll = l - 3 + k;
        if (ll >= 0) {
            float4 xv = *(const float4*)&g_zx[(size_t)(m - 3 + k) * NPROJ + DINNER + c];
            acc.x = fmaf(xv.x, wk0[k], acc.x);
            acc.y = fmaf(xv.y, wk1[k], acc.y);
            acc.z = fmaf(xv.z, wk2[k], acc.z);
            acc.w = fmaf(xv.w, wk3[k], acc.w);
        }
    }
    acc.x *= 1.f / (1.f + __expf(-acc.x));
    acc.y *= 1.f / (1.f + __expf(-acc.y));
    acc.z *= 1.f / (1.f + __expf(-acc.z));
    acc.w *= 1.f / (1.f + __expf(-acc.w));
    *(float4*)&g_xc[(size_t)m * CONVD + c] = acc;
}

// ---------------------------------------------------------------------------
// EXACT fp32 dt path, 16 tokens per CTA (weights loaded once per warp,
// x rows staged in smem). Arithmetic per token identical to per-token version.
// ---------------------------------------------------------------------------
#define DTB 16

__global__ __launch_bounds__(256)
void dt_exact(const float* __restrict__ x, const float* __restrict__ wi,
              const float* __restrict__ dtb, const float* __restrict__ alog)
{
    __shared__ __align__(16) float xrow[DTB][DMODEL];   // 48 KB
    int m0 = blockIdx.x * DTB;
    int tid = threadIdx.x;
    // stage 16 x rows (16*768/4 = 3072 float4)
    for (int i = tid; i < DTB * DMODEL / 4; i += 256)
        ((float4*)xrow)[i] = ((const float4*)(x + (size_t)m0 * DMODEL))[i];
    __syncthreads();

    int w = tid >> 5, lane = tid & 31;
#pragma unroll
    for (int hh = 0; hh < 3; hh++) {
        int h = w + hh * 8;
        float A = -expf(alog[h]);
        float db = dtb[h];
        const float4* wr4 = (const float4*)(wi + (size_t)(DINNER + CONVD + h) * DMODEL);
        float4 wreg[6];
#pragma unroll
        for (int j = 0; j < 6; j++) wreg[j] = wr4[lane + j * 32];

        for (int t = 0; t < DTB; t++) {
            const float4* xr4 = (const float4*)xrow[t];
            float dot = 0.f;
#pragma unroll
            for (int j = 0; j < 6; j++) {
                float4 a = xr4[lane + j * 32];
                float4 b = wreg[j];
                dot = fmaf(a.x, b.x, fmaf(a.y, b.y, fmaf(a.z, b.z, fmaf(a.w, b.w, dot))));
            }
#pragma unroll
            for (int o = 16; o > 0; o >>= 1) dot += __shfl_xor_sync(0xffffffffu, dot, o);
            if (lane == 0) {
                int m = m0 + t;
                float v = dot + db;
                float sp = fmaxf(v, 0.f) + log1pf(expf(-fabsf(v)));
                int b = m / LSEQ, l = m % LSEQ;
                g_dtdA[(size_t)(b * NH + h) * LSEQ + l] = make_float2(sp, expf(sp * A));
            }
        }
    }
}

// ---------------------------------------------------------------------------
// Chunked selective SSM scan (Round-12 configuration: 3 chunks, 2 CTAs/SM).
// ---------------------------------------------------------------------------
#define NSTG 16
#define STGF 336
#define LCH  688

__global__ __launch_bounds__(256, 2)
void scan_kernel(const float* __restrict__ Dv)
{
    __shared__ __align__(16) float sh[NSTG][STGF];
    __shared__ __align__(16) float yb[8][1024];
    uint32_t sb = smem_u32(sh);
    int bc = blockIdx.x;
    int bh = bc % 96;
    int c  = bc / 96;
    int t0 = c * LCH;
    int T  = (c < 2) ? LCH : (LSEQ - 2 * LCH);
    int b = bh / NH, h = bh % NH;
    int tid = threadIdx.x;
    int pg = tid >> 4, nq = tid & 15;
    int xorm = (pg & 1) * 16;
    float dh0 = (nq == 0) ? Dv[h] : 0.f;

    const char* src = nullptr;
    uint32_t dsto = 0;
    size_t stride = (size_t)CONVD * 4;
    const char* xcb = (const char*)(g_xc + ((size_t)b * LSEQ + t0) * CONVD);
    if (tid < 16) {
        src = xcb + (size_t)h * HD * 4 + tid * 16;
        dsto = tid * 16;
    } else if (tid < 48) {
        int t = tid - 16;
        src = xcb + (size_t)DINNER * 4 + t * 16;
        dsto = 256 + (uint32_t)((((t & 1) * 16) + (t >> 1)) * 16);
    } else if (tid < 80) {
        int t = tid - 48;
        src = xcb + (size_t)(DINNER + DST) * 4 + t * 16;
        dsto = 768 + (uint32_t)((((t & 1) * 16) + (t >> 1)) * 16);
    } else if (tid == 80) {
        src = (const char*)(g_dtdA + (size_t)bh * LSEQ + t0);
        dsto = 1280;
        stride = 8;
    }

    auto issue_group = [&](int gq) {
#pragma unroll
        for (int q = 0; q < 4; q++) {
            int step = 4 * gq + q;
            if (step < T && tid <= 80) {
                uint32_t d = sb + (uint32_t)((step & (NSTG - 1)) * (STGF * 4)) + dsto;
                if (tid < 80) cp16(d, src); else cp8(d, src);
                src += stride;
            }
        }
        cp_commit();
    };

    issue_group(0); issue_group(1); issue_group(2);

    ull st[4][4];
#pragma unroll
    for (int pi = 0; pi < 4; pi++)
#pragma unroll
        for (int k = 0; k < 4; k++) st[pi][k] = 0ull;

    float* ybase = g_y + ((size_t)b * LSEQ + t0) * DINNER + h * HD;
    float run = 1.f;
    float* prefp = g_pref + (size_t)bh * LSEQ + t0;

    for (int g = 0; g < T / 4; g++) {
        cp_wait2();
        __syncthreads();
        issue_group(g + 3);

#pragma unroll
        for (int q = 0; q < 4; q++) {
            int l = 4 * g + q;
            const float* bp = sh[l & (NSTG - 1)];
            float4 xv = *(const float4*)(bp + 4 * pg);
            float2 da = *(const float2*)(bp + 320);
            ull dA2 = pk2(da.y, da.y);
            float xs[4] = {xv.x, xv.y, xv.z, xv.w};
            ull dtx2[4];
#pragma unroll
            for (int pi = 0; pi < 4; pi++) {
                float d = da.x * xs[pi];
                dtx2[pi] = pk2(d, d);
            }
            const ulonglong2* B4 = (const ulonglong2*)(bp + 64);
            const ulonglong2* C4 = (const ulonglong2*)(bp + 192);
            ull bb[4], cc[4];
#pragma unroll
            for (int j = 0; j < 2; j++) {
                ulonglong2 bv = B4[j * 16 + nq];
                ulonglong2 cv = C4[j * 16 + nq];
                bb[2*j] = bv.x; bb[2*j+1] = bv.y;
                cc[2*j] = cv.x; cc[2*j+1] = cv.y;
            }
            float* yrow = yb[l & 7] + 64 * pg;
#pragma unroll
            for (int pi = 0; pi < 4; pi++) {
                ull acc2 = 0ull;
#pragma unroll
                for (int k = 0; k < 4; k++) {
                    st[pi][k] = f2fma(st[pi][k], dA2, f2mul(dtx2[pi], bb[k]));
                    acc2 = f2fma(st[pi][k], cc[k], acc2);
                }
                float2 av = upk2(acc2);
                yrow[(16 * pi + nq) ^ xorm] = fmaf(dh0, xs[pi], av.x + av.y);
            }
            if (tid == 255 && c > 0) {
                run *= da.y;
                prefp[l] = run;
            }
        }

        if (g & 1) {
            __syncthreads();
#pragma unroll
            for (int k = 0; k < 2; k++) {
                int o = tid + 256 * k;
                int s_ = o >> 6, p = o & 63;
                int rpg = p >> 2, rpi = p & 3;
                const float4* r4 = (const float4*)(yb[s_] + 64 * rpg
                                                   + (16 * (rpi ^ (rpg & 1))));
                float4 v0 = r4[0], v1 = r4[1], v2 = r4[2], v3 = r4[3];
                float acc = (((v0.x + v0.y) + (v0.z + v0.w))
                           + ((v1.x + v1.y) + (v1.z + v1.w)))
                          + (((v2.x + v2.y) + (v2.z + v2.w))
                           + ((v3.x + v3.y) + (v3.z + v3.w)));
                int l0 = 4 * (g - 1);
                ybase[(size_t)(l0 + s_) * DINNER + p] = acc;
            }
        }
    }

    if (c < 2) {
        float* cs = g_cstate + ((size_t)bh * 2 + c) * 8192;
#pragma unroll
        for (int pi = 0; pi < 4; pi++) {
            int p = 4 * pg + pi;
#pragma unroll
            for (int j = 0; j < 2; j++) {
                float2 a = upk2(st[pi][2*j]);
                float2 d = upk2(st[pi][2*j+1]);
                float4 v = make_float4(a.x, a.y, d.x, d.y);
                *(float4*)(cs + p * 128 + 8 * nq + 4 * j) = v;
            }
        }
    }
}

// ---------------------------------------------------------------------------
// Fix-up (Round-12 configuration).
// ---------------------------------------------------------------------------
#define FSTG 16
#define FSTGF 132

__global__ __launch_bounds__(512, 2)
void fixup_kernel()
{
    __shared__ __align__(16) float sh[FSTG][FSTGF];
    __shared__ __align__(16) float yb[8][512];
    uint32_t sb = smem_u32(sh);
    int bx = blockIdx.x;
    int bh = bx % 96;
    int r  = bx / 96;
    int c  = 1 + (r >> 1);
    int half = r & 1;
    int Tc = (c == 1) ? LCH : (LSEQ - 2 * LCH);
    int Th = Tc / 2;
    int t0 = c * LCH + half * Th;
    int b = bh / NH, h = bh % NH;
    int tid = threadIdx.x;
    int p = tid >> 3, nb = tid & 7;

    float q1 = (c == 2) ? g_pref[(size_t)bh * LSEQ + 2 * LCH - 1] : 0.f;
    ull sini[8];
    {
        const float4* s1 = (const float4*)(g_cstate + ((size_t)bh * 2 + (c - 1)) * 8192
                                           + p * 128 + nb * 16);
        const float4* s0 = (const float4*)(g_cstate + ((size_t)bh * 2) * 8192
                                           + p * 128 + nb * 16);
#pragma unroll
        for (int i = 0; i < 4; i++) {
            float4 v = s1[i];
            if (c == 2) {
                float4 w = s0[i];
                v.x = fmaf(q1, w.x, v.x); v.y = fmaf(q1, w.y, v.y);
                v.z = fmaf(q1, w.z, v.z); v.w = fmaf(q1, w.w, v.w);
            }
            sini[2*i]   = pk2(v.x, v.y);
            sini[2*i+1] = pk2(v.z, v.w);
        }
    }

    const char* src = nullptr;
    uint32_t dsto = 0;
    size_t stride = (size_t)CONVD * 4;
    if (tid < 32) {
        src = (const char*)(g_xc + ((size_t)b * LSEQ + t0) * CONVD + DINNER + DST) + tid * 16;
        dsto = (uint32_t)((((tid & 3) * 8) + (tid >> 2)) * 16);
    } else if (tid == 32) {
        src = (const char*)(g_pref + (size_t)bh * LSEQ + t0);
        dsto = 512;
        stride = 4;
    }

    auto issue_group = [&](int gq) {
#pragma unroll
        for (int q = 0; q < 4; q++) {
            int step = 4 * gq + q;
            if (step < Th && tid <= 32) {
                uint32_t d = sb + (uint32_t)((step & (FSTG - 1)) * (FSTGF * 4)) + dsto;
                if (tid < 32) cp16(d, src); else cp4(d, src);
                src += stride;
            }
        }
        cp_commit();
    };
    issue_group(0); issue_group(1); issue_group(2);

    float* ybase = g_y + ((size_t)b * LSEQ + t0) * DINNER + h * HD;
    int rs = tid >> 6, rp = tid & 63;

    for (int g = 0; g < Th / 4; g++) {
        cp_wait2();
        __syncthreads();
        issue_group(g + 3);

#pragma unroll
        for (int q = 0; q < 4; q++) {
            int l = 4 * g + q;
            const float* bp = sh[l & (FSTG - 1)];
            const ulonglong2* C4 = (const ulonglong2*)bp;
            ull cc[8];
#pragma unroll
            for (int j = 0; j < 4; j++) {
                ulonglong2 cv = C4[j * 8 + nb];
                cc[2*j] = cv.x; cc[2*j+1] = cv.y;
            }
            ull acc2 = 0ull;
#pragma unroll
            for (int i = 0; i < 8; i++) acc2 = f2fma(sini[i], cc[i], acc2);
            float2 av = upk2(acc2);
            yb[l & 7][tid] = (av.x + av.y) * bp[128];
        }

        if (g & 1) {
            __syncthreads();
            const float4* r4 = (const float4*)(yb[rs] + rp * 8);
            float4 v0 = r4[0], v1 = r4[1];
            float acc = ((v0.x + v0.y) + (v0.z + v0.w))
                      + ((v1.x + v1.y) + (v1.z + v1.w));
            int l0 = 4 * (g - 1);
            float* yp = ybase + (size_t)(l0 + rs) * DINNER + rp;
            *yp += acc;
        }
    }
}

// ---------------------------------------------------------------------------
// gate + rmsnorm, emits fp16
// ---------------------------------------------------------------------------
__global__ __launch_bounds__(384)
void gate_norm(const float* __restrict__ nw)
{
    __shared__ float warpsum[12];
    __shared__ float stot;
    int m = blockIdx.x;
    int tid = threadIdx.x;
    float4 yv = ((const float4*)(g_y + (size_t)m * DINNER))[tid];
    float4 zv = ((const float4*)(g_zx + (size_t)m * NPROJ))[tid];
    float4 v;
    v.x = yv.x * (zv.x / (1.f + __expf(-zv.x)));
    v.y = yv.y * (zv.y / (1.f + __expf(-zv.y)));
    v.z = yv.z * (zv.z / (1.f + __expf(-zv.z)));
    v.w = yv.w * (zv.w / (1.f + __expf(-zv.w)));
    float ss = fmaf(v.x, v.x, fmaf(v.y, v.y, fmaf(v.z, v.z, v.w * v.w)));
#pragma unroll
    for (int o = 16; o > 0; o >>= 1) ss += __shfl_xor_sync(0xffffffffu, ss, o);
    if ((tid & 31) == 0) warpsum[tid >> 5] = ss;
    __syncthreads();
    if (tid == 0) {
        float t = 0.f;
#pragma unroll
        for (int w = 0; w < 12; w++) t += warpsum[w];
        stot = t;
    }
    __syncthreads();
    float scale = rsqrtf(stot / (float)DINNER + 1e-5f);
    float4 nv = ((const float4*)nw)[tid];
    v.x *= scale * nv.x; v.y *= scale * nv.y;
    v.z *= scale * nv.z; v.w *= scale * nv.w;
    __half2 h0 = __floats2half2_rn(v.x, v.y);
    __half2 h1 = __floats2half2_rn(v.z, v.w);
    ((uint2*)(g_Yh + (size_t)m * DINNER))[tid] =
        make_uint2(*(uint32_t*)&h0, *(uint32_t*)&h1);
}

// ---------------------------------------------------------------------------
extern "C" void kernel_launch(void* const* d_in, const int* in_sizes, int n_in,
                              void* d_out, int out_size)
{
    const float* x    = (const float*)d_in[0];
    const float* wi   = (const float*)d_in[1];
    const float* cw   = (const float*)d_in[2];
    const float* cb   = (const float*)d_in[3];
    const float* dtb  = (const float*)d_in[4];
    const float* alog = (const float*)d_in[5];
    const float* Dv   = (const float*)d_in[6];
    const float* nw   = (const float*)d_in[7];
    const float* wo   = (const float*)d_in[8];
    float* out = (float*)d_out;

    float *zx;
    __half *xh, *wih, *yh, *woh;
    cudaGetSymbolAddress((void**)&zx,  g_zx);
    cudaGetSymbolAddress((void**)&xh,  g_Xh);
    cudaGetSymbolAddress((void**)&wih, g_Wih);
    cudaGetSymbolAddress((void**)&yh,  g_Yh);
    cudaGetSymbolAddress((void**)&woh, g_Woh);

    static const int smem_bytes = 2 * STAGE_B;  // 110592 B
    cudaFuncSetAttribute(mma_gemm, cudaFuncAttributeMaxDynamicSharedMemorySize, smem_bytes);

    dim3 blk(256);

    conv_hi16<<<(M_TOK * DMODEL / 4 + 255) / 256, blk>>>(x, xh,
                                                         M_TOK * DMODEL / 4, M_TOK * DMODEL / 4);
    conv_hi16<<<(NPAD * DMODEL / 4 + 255) / 256, blk>>>(wi, wih,
                                                        NPROJ * DMODEL / 4, NPAD * DMODEL / 4);
    conv_hi16<<<(DMODEL * DINNER / 4 + 255) / 256, blk>>>(wo, woh,
                                                          DMODEL * DINNER / 4, DMODEL * DINNER / 4);

    // in_proj (fp16 1-pass; dt recomputed exactly below)
    mma_gemm<<<dim3(NPAD / 128, M_TOK / 256), blk, smem_bytes>>>(
        xh, wih, nullptr, zx, NPROJ, DMODEL);

    dt_exact<<<M_TOK / DTB, blk>>>(x, wi, dtb, alog);
    conv_silu<<<(M_TOK * (CONVD / 4) + 255) / 256, blk>>>(cw, cb);
    scan_kernel<<<288, 256>>>(Dv);
    fixup_kernel<<<384, 512>>>();
    gate_norm<<<M_TOK, 384>>>(nw);

    // out_proj + residual (fp16 1-pass)
    mma_gemm<<<dim3(DMODEL / 128, M_TOK / 256), blk, smem_bytes>>>(
        yh, woh, x, out, DMODEL, DINNER);
}

// round 15
// speedup vs baseline: 1.0627x; 1.0374x over previous
#include <cuda_runtime.h>
#include <cuda_fp16.h>
#include <cstdint>

#define M_TOK 8192
#define DMODEL 768
#define DINNER 1536
#define CONVD  1792
#define NH     24
#define HD     64
#define DST    128
#define NPROJ  3352
#define NPAD   3456
#define LSEQ   2048

// ---------------- device scratch (no allocation allowed) ----------------
__device__ float g_zx[M_TOK * NPROJ];    // in_proj output (z | xBC | dt-unused)
__device__ float g_xc[M_TOK * CONVD];    // conv+silu output (xh | B | C)
__device__ float2 g_dtdA[96 * LSEQ];     // packed (dt, dA) per (b*NH+h, l)
__device__ float g_y [M_TOK * DINNER];   // scan output (no D skip; added in gate_norm)
__device__ float g_cstate[96 * 2 * 64 * 128];  // per-chunk final local state
__device__ float g_pref[96 * LSEQ];            // per-chunk dA prefix products

__device__ __half g_Xh[M_TOK * DMODEL];
__device__ __half g_Wih[NPAD * DMODEL];
__device__ __half g_Yh[M_TOK * DINNER];
__device__ __half g_Woh[DMODEL * DINNER];

typedef unsigned long long ull;

__device__ __forceinline__ uint32_t smem_u32(const void* p) {
    uint32_t a;
    asm("{ .reg .u64 t; cvta.to.shared.u64 t, %1; cvt.u32.u64 %0, t; }"
        : "=r"(a) : "l"(p));
    return a;
}

__device__ __forceinline__ void cp16(uint32_t dst, const void* src) {
    asm volatile("cp.async.cg.shared.global [%0], [%1], 16;"
                 :: "r"(dst), "l"(src) : "memory");
}
__device__ __forceinline__ void cp8(uint32_t dst, const void* src) {
    asm volatile("cp.async.ca.shared.global [%0], [%1], 8;"
                 :: "r"(dst), "l"(src) : "memory");
}
__device__ __forceinline__ void cp4(uint32_t dst, const void* src) {
    asm volatile("cp.async.ca.shared.global [%0], [%1], 4;"
                 :: "r"(dst), "l"(src) : "memory");
}
__device__ __forceinline__ void cp_commit() {
    asm volatile("cp.async.commit_group;" ::: "memory");
}
__device__ __forceinline__ void cp_wait0() {
    asm volatile("cp.async.wait_group 0;" ::: "memory");
}
__device__ __forceinline__ void cp_wait1() {
    asm volatile("cp.async.wait_group 1;" ::: "memory");
}
__device__ __forceinline__ void cp_wait2() {
    asm volatile("cp.async.wait_group 2;" ::: "memory");
}

__device__ __forceinline__ void ldmx4(uint32_t* r, uint32_t addr) {
    asm volatile("ldmatrix.sync.aligned.m8n8.x4.shared.b16 {%0,%1,%2,%3}, [%4];"
                 : "=r"(r[0]), "=r"(r[1]), "=r"(r[2]), "=r"(r[3]) : "r"(addr));
}

__device__ __forceinline__ void mma16816h(float* c, const uint32_t* a, const uint32_t* b) {
    asm volatile(
        "mma.sync.aligned.m16n8k16.row.col.f32.f16.f16.f32 "
        "{%0,%1,%2,%3}, {%4,%5,%6,%7}, {%8,%9}, {%0,%1,%2,%3};"
        : "+f"(c[0]), "+f"(c[1]), "+f"(c[2]), "+f"(c[3])
        : "r"(a[0]), "r"(a[1]), "r"(a[2]), "r"(a[3]), "r"(b[0]), "r"(b[1]));
}

// ---------------------------------------------------------------------------
// fp16 1-pass GEMM (NT): C = fp16(A) * fp16(B)^T, fp32 accumulate.
// CTA tile 256x128, 8 warps (warp tile 64x64), K-chunk 64, 2-stage ring.
// ---------------------------------------------------------------------------
#define BK      64
#define LDT_B   144
#define ROW_A   256
#define ROW_BT  128
#define STAGE_B ((ROW_A + ROW_BT) * LDT_B)   // 55296

__global__ __launch_bounds__(256, 1)
void mma_gemm(const __half* __restrict__ Ah_, const __half* __restrict__ Bh_,
              const float* __restrict__ R, float* __restrict__ C,
              int Nact, int K)
{
    extern __shared__ char smem[];
    uint32_t sb = smem_u32(smem);
    int tid  = threadIdx.x;
    int wid  = tid >> 5, lane = tid & 31;
    int wm   = wid & 3, wn = wid >> 2;
    int m0   = blockIdx.y * 256, n0 = blockIdx.x * 128;

    const size_t rowK = (size_t)K * 2;

    auto load_stage = [&](int s, int k0) {
        uint32_t d0 = sb + s * STAGE_B;
#pragma unroll
        for (int i = 0; i < 12; i++) {
            int idx = tid + i * 256;
            int row = idx >> 3, ch = idx & 7;
            const char* src;
            if (row < ROW_A)
                src = (const char*)Ah_ + (size_t)(m0 + row) * rowK + k0 * 2;
            else
                src = (const char*)Bh_ + (size_t)(n0 + row - ROW_A) * rowK + k0 * 2;
            cp16(d0 + row * LDT_B + ch * 16, src + ch * 16);
        }
        cp_commit();
    };

    float acc[4][8][4];
#pragma unroll
    for (int mt = 0; mt < 4; mt++)
#pragma unroll
        for (int nt = 0; nt < 8; nt++)
#pragma unroll
            for (int j = 0; j < 4; j++) acc[mt][nt][j] = 0.f;

    int nch = K / BK;
    load_stage(0, 0);

    int a_row = wm * 64 + (lane & 7) + ((lane >> 3) & 1) * 8;
    int a_cb  = ((lane >> 4) & 1) * 16;
    int b_row = wn * 64 + ((lane >> 4) & 1) * 8 + (lane & 7);
    int b_cb  = ((lane >> 3) & 1) * 16;

    for (int c = 0; c < nch; c++) {
        if (c + 1 < nch) { load_stage((c + 1) & 1, (c + 1) * BK); cp_wait1(); }
        else             { cp_wait0(); }
        __syncthreads();

        uint32_t st = sb + (c & 1) * STAGE_B;
        uint32_t Ah = st;
        uint32_t Bh = st + ROW_A * LDT_B;

#pragma unroll
        for (int kk = 0; kk < 4; kk++) {
            int kb = kk * 32;
            uint32_t ah[4][4];
#pragma unroll
            for (int mt = 0; mt < 4; mt++) {
                uint32_t off = (uint32_t)((a_row + mt * 16) * LDT_B + kb + a_cb);
                ldmx4(ah[mt], Ah + off);
            }
            uint32_t bh[8][2];
#pragma unroll
            for (int q = 0; q < 4; q++) {
                uint32_t off = (uint32_t)((b_row + q * 16) * LDT_B + kb + b_cb);
                uint32_t r[4];
                ldmx4(r, Bh + off);
                bh[2*q][0] = r[0]; bh[2*q][1] = r[1];
                bh[2*q+1][0] = r[2]; bh[2*q+1][1] = r[3];
            }
#pragma unroll
            for (int mt = 0; mt < 4; mt++)
#pragma unroll
                for (int nt = 0; nt < 8; nt++)
                    mma16816h(acc[mt][nt], ah[mt], bh[nt]);
        }
        __syncthreads();
    }

    int l4 = lane >> 2, l2 = (lane & 3) * 2;
#pragma unroll
    for (int mt = 0; mt < 4; mt++) {
        int gm = m0 + wm * 64 + mt * 16 + l4;
#pragma unroll
        for (int nt = 0; nt < 8; nt++) {
            int gn = n0 + wn * 64 + nt * 8 + l2;
            if (gn < Nact) {
                size_t o0 = (size_t)gm * Nact + gn;
                size_t o1 = (size_t)(gm + 8) * Nact + gn;
                float2 v0 = make_float2(acc[mt][nt][0], acc[mt][nt][1]);
                float2 v1 = make_float2(acc[mt][nt][2], acc[mt][nt][3]);
                if (R) {
                    const float2 r0 = *(const float2*)&R[o0];
                    const float2 r1 = *(const float2*)&R[o1];
                    v0.x += r0.x; v0.y += r0.y; v1.x += r1.x; v1.y += r1.y;
                }
                *(float2*)&C[o0] = v0;
                *(float2*)&C[o1] = v1;
            }
        }
    }
}

// ---------------------------------------------------------------------------
// fp32 -> fp16 convert (float4-vectorized, zero-padded)
// ---------------------------------------------------------------------------
__global__ void conv_hi16(const float* __restrict__ w, __half* __restrict__ hi,
                          int nsrc4, int ntot4)
{
    int i = blockIdx.x * blockDim.x + threadIdx.x;
    if (i >= ntot4) return;
    float4 v = make_float4(0.f, 0.f, 0.f, 0.f);
    if (i < nsrc4) v = ((const float4*)w)[i];
    __half2 h0 = __floats2half2_rn(v.x, v.y);
    __half2 h1 = __floats2half2_rn(v.z, v.w);
    ((uint2*)hi)[i] = make_uint2(*(uint32_t*)&h0, *(uint32_t*)&h1);
}

// ---------------------------------------------------------------------------
__device__ __forceinline__ ull pk2(float x, float y) {
    ull r; asm("mov.b64 %0,{%1,%2};" : "=l"(r) : "f"(x), "f"(y)); return r;
}
__device__ __forceinline__ float2 upk2(ull v) {
    float2 r; asm("mov.b64 {%0,%1},%2;" : "=f"(r.x), "=f"(r.y) : "l"(v)); return r;
}
__device__ __forceinline__ ull f2fma(ull a, ull b, ull c) {
    ull d; asm("fma.rn.f32x2 %0,%1,%2,%3;" : "=l"(d) : "l"(a), "l"(b), "l"(c)); return d;
}
__device__ __forceinline__ ull f2mul(ull a, ull b) {
    ull d; asm("mul.rn.f32x2 %0,%1,%2;" : "=l"(d) : "l"(a), "l"(b)); return d;
}

// ---------------------------------------------------------------------------
// Causal depthwise conv1d + SiLU: 4 timesteps x 4 channels per thread.
// 7 tap loads produce 4 outputs (tap reuse); per-output FLOP order identical
// to the reference (k = 0..3 ascending).
// ---------------------------------------------------------------------------
__global__ void conv_silu(const float* __restrict__ cw, const float* __restrict__ cb)
{
    int idx = blockIdx.x * blockDim.x + threadIdx.x;
    if (idx >= (M_TOK / 4) * (CONVD / 4)) return;
    int c4 = idx % (CONVD / 4), mg = idx / (CONVD / 4);
    int c = c4 * 4;
    int m0 = mg * 4;                 // 4 consecutive tokens, same sequence
    int l0 = m0 & (LSEQ - 1);

    float4 w0 = ((const float4*)cw)[c];
    float4 w1 = ((const float4*)cw)[c + 1];
    float4 w2 = ((const float4*)cw)[c + 2];
    float4 w3 = ((const float4*)cw)[c + 3];
    const float* wk0 = (const float*)&w0;
    const float* wk1 = (const float*)&w1;
    const float* wk2 = (const float*)&w2;
    const float* wk3 = (const float*)&w3;
    float4 bias = *(const float4*)&cb[c];

    float4 tap[7];
#pragma unroll
    for (int j = 0; j < 7; j++) {
        int l = l0 - 3 + j;
        if (l >= 0 && j < 3 + 4)     // j<7 always; guard only l>=0
            tap[j] = (l >= 0) ? *(const float4*)&g_zx[(size_t)(m0 - 3 + j) * NPROJ + DINNER + c]
                              : make_float4(0.f, 0.f, 0.f, 0.f);
        if (l < 0) tap[j] = make_float4(0.f, 0.f, 0.f, 0.f);
    }

#pragma unroll
    for (int t = 0; t < 4; t++) {
        float4 acc = bias;
#pragma unroll
        for (int k = 0; k < 4; k++) {
            float4 xv = tap[t + k];
            acc.x = fmaf(xv.x, wk0[k], acc.x);
            acc.y = fmaf(xv.y, wk1[k], acc.y);
            acc.z = fmaf(xv.z, wk2[k], acc.z);
            acc.w = fmaf(xv.w, wk3[k], acc.w);
        }
        acc.x *= 1.f / (1.f + __expf(-acc.x));
        acc.y *= 1.f / (1.f + __expf(-acc.y));
        acc.z *= 1.f / (1.f + __expf(-acc.z));
        acc.w *= 1.f / (1.f + __expf(-acc.w));
        *(float4*)&g_xc[(size_t)(m0 + t) * CONVD + c] = acc;
    }
}

// ---------------------------------------------------------------------------
// EXACT fp32 dt path, 16 tokens per CTA.
// ---------------------------------------------------------------------------
#define DTB 16

__global__ __launch_bounds__(256)
void dt_exact(const float* __restrict__ x, const float* __restrict__ wi,
              const float* __restrict__ dtb, const float* __restrict__ alog)
{
    __shared__ __align__(16) float xrow[DTB][DMODEL];   // 48 KB
    int m0 = blockIdx.x * DTB;
    int tid = threadIdx.x;
    for (int i = tid; i < DTB * DMODEL / 4; i += 256)
        ((float4*)xrow)[i] = ((const float4*)(x + (size_t)m0 * DMODEL))[i];
    __syncthreads();

    int w = tid >> 5, lane = tid & 31;
#pragma unroll
    for (int hh = 0; hh < 3; hh++) {
        int h = w + hh * 8;
        float A = -expf(alog[h]);
        float db = dtb[h];
        const float4* wr4 = (const float4*)(wi + (size_t)(DINNER + CONVD + h) * DMODEL);
        float4 wreg[6];
#pragma unroll
        for (int j = 0; j < 6; j++) wreg[j] = wr4[lane + j * 32];

        for (int t = 0; t < DTB; t++) {
            const float4* xr4 = (const float4*)xrow[t];
            float dot = 0.f;
#pragma unroll
            for (int j = 0; j < 6; j++) {
                float4 a = xr4[lane + j * 32];
                float4 b = wreg[j];
                dot = fmaf(a.x, b.x, fmaf(a.y, b.y, fmaf(a.z, b.z, fmaf(a.w, b.w, dot))));
            }
#pragma unroll
            for (int o = 16; o > 0; o >>= 1) dot += __shfl_xor_sync(0xffffffffu, dot, o);
            if (lane == 0) {
                int m = m0 + t;
                float v = dot + db;
                float sp = fmaxf(v, 0.f) + log1pf(expf(-fabsf(v)));
                int b = m / LSEQ, l = m % LSEQ;
                g_dtdA[(size_t)(b * NH + h) * LSEQ + l] = make_float2(sp, expf(sp * A));
            }
        }
    }
}

// ---------------------------------------------------------------------------
// Chunked selective SSM scan (3 chunks, 2 CTAs/SM). No D-skip (in gate_norm).
// ---------------------------------------------------------------------------
#define NSTG 16
#define STGF 336
#define LCH  688

__global__ __launch_bounds__(256, 2)
void scan_kernel()
{
    __shared__ __align__(16) float sh[NSTG][STGF];
    __shared__ __align__(16) float yb[8][1024];
    uint32_t sb = smem_u32(sh);
    int bc = blockIdx.x;
    int bh = bc % 96;
    int c  = bc / 96;
    int t0 = c * LCH;
    int T  = (c < 2) ? LCH : (LSEQ - 2 * LCH);
    int b = bh / NH, h = bh % NH;
    int tid = threadIdx.x;
    int pg = tid >> 4, nq = tid & 15;
    int xorm = (pg & 1) * 16;

    const char* src = nullptr;
    uint32_t dsto = 0;
    size_t stride = (size_t)CONVD * 4;
    const char* xcb = (const char*)(g_xc + ((size_t)b * LSEQ + t0) * CONVD);
    if (tid < 16) {
        src = xcb + (size_t)h * HD * 4 + tid * 16;
        dsto = tid * 16;
    } else if (tid < 48) {
        int t = tid - 16;
        src = xcb + (size_t)DINNER * 4 + t * 16;
        dsto = 256 + (uint32_t)((((t & 1) * 16) + (t >> 1)) * 16);
    } else if (tid < 80) {
        int t = tid - 48;
        src = xcb + (size_t)(DINNER + DST) * 4 + t * 16;
        dsto = 768 + (uint32_t)((((t & 1) * 16) + (t >> 1)) * 16);
    } else if (tid == 80) {
        src = (const char*)(g_dtdA + (size_t)bh * LSEQ + t0);
        dsto = 1280;
        stride = 8;
    }

    auto issue_group = [&](int gq) {
#pragma unroll
        for (int q = 0; q < 4; q++) {
            int step = 4 * gq + q;
            if (step < T && tid <= 80) {
                uint32_t d = sb + (uint32_t)((step & (NSTG - 1)) * (STGF * 4)) + dsto;
                if (tid < 80) cp16(d, src); else cp8(d, src);
                src += stride;
            }
        }
        cp_commit();
    };

    issue_group(0); issue_group(1); issue_group(2);

    ull st[4][4];
#pragma unroll
    for (int pi = 0; pi < 4; pi++)
#pragma unroll
        for (int k = 0; k < 4; k++) st[pi][k] = 0ull;

    float* ybase = g_y + ((size_t)b * LSEQ + t0) * DINNER + h * HD;
    float run = 1.f;
    float* prefp = g_pref + (size_t)bh * LSEQ + t0;

    for (int g = 0; g < T / 4; g++) {
        cp_wait2();
        __syncthreads();
        issue_group(g + 3);

#pragma unroll
        for (int q = 0; q < 4; q++) {
            int l = 4 * g + q;
            const float* bp = sh[l & (NSTG - 1)];
            float4 xv = *(const float4*)(bp + 4 * pg);
            float2 da = *(const float2*)(bp + 320);
            ull dA2 = pk2(da.y, da.y);
            float xs[4] = {xv.x, xv.y, xv.z, xv.w};
            ull dtx2[4];
#pragma unroll
            for (int pi = 0; pi < 4; pi++) {
                float d = da.x * xs[pi];
                dtx2[pi] = pk2(d, d);
            }
            const ulonglong2* B4 = (const ulonglong2*)(bp + 64);
            const ulonglong2* C4 = (const ulonglong2*)(bp + 192);
            ull bb[4], cc[4];
#pragma unroll
            for (int j = 0; j < 2; j++) {
                ulonglong2 bv = B4[j * 16 + nq];
                ulonglong2 cv = C4[j * 16 + nq];
                bb[2*j] = bv.x; bb[2*j+1] = bv.y;
                cc[2*j] = cv.x; cc[2*j+1] = cv.y;
            }
            float* yrow = yb[l & 7] + 64 * pg;
#pragma unroll
            for (int pi = 0; pi < 4; pi++) {
                ull acc2 = 0ull;
#pragma unroll
                for (int k = 0; k < 4; k++) {
                    st[pi][k] = f2fma(st[pi][k], dA2, f2mul(dtx2[pi], bb[k]));
                    acc2 = f2fma(st[pi][k], cc[k], acc2);
                }
                float2 av = upk2(acc2);
                yrow[(16 * pi + nq) ^ xorm] = av.x + av.y;
            }
            if (tid == 255 && c > 0) {
                run *= da.y;
                prefp[l] = run;
            }
        }

        if (g & 1) {
            __syncthreads();
#pragma unroll
            for (int k = 0; k < 2; k++) {
                int o = tid + 256 * k;
                int s_ = o >> 6, p = o & 63;
                int rpg = p >> 2, rpi = p & 3;
                const float4* r4 = (const float4*)(yb[s_] + 64 * rpg
                                                   + (16 * (rpi ^ (rpg & 1))));
                float4 v0 = r4[0], v1 = r4[1], v2 = r4[2], v3 = r4[3];
                float acc = (((v0.x + v0.y) + (v0.z + v0.w))
                           + ((v1.x + v1.y) + (v1.z + v1.w)))
                          + (((v2.x + v2.y) + (v2.z + v2.w))
                           + ((v3.x + v3.y) + (v3.z + v3.w)));
                int l0 = 4 * (g - 1);
                ybase[(size_t)(l0 + s_) * DINNER + p] = acc;
            }
        }
    }

    if (c < 2) {
        float* cs = g_cstate + ((size_t)bh * 2 + c) * 8192;
#pragma unroll
        for (int pi = 0; pi < 4; pi++) {
            int p = 4 * pg + pi;
#pragma unroll
            for (int j = 0; j < 2; j++) {
                float2 a = upk2(st[pi][2*j]);
                float2 d = upk2(st[pi][2*j+1]);
                float4 v = make_float4(a.x, a.y, d.x, d.y);
                *(float4*)(cs + p * 128 + 8 * nq + 4 * j) = v;
            }
        }
    }
}

// ---------------------------------------------------------------------------
// Fix-up (unchanged).
// ---------------------------------------------------------------------------
#define FSTG 16
#define FSTGF 132

__global__ __launch_bounds__(512, 2)
void fixup_kernel()
{
    __shared__ __align__(16) float sh[FSTG][FSTGF];
    __shared__ __align__(16) float yb[8][512];
    uint32_t sb = smem_u32(sh);
    int bx = blockIdx.x;
    int bh = bx % 96;
    int r  = bx / 96;
    int c  = 1 + (r >> 1);
    int half = r & 1;
    int Tc = (c == 1) ? LCH : (LSEQ - 2 * LCH);
    int Th = Tc / 2;
    int t0 = c * LCH + half * Th;
    int b = bh / NH, h = bh % NH;
    int tid = threadIdx.x;
    int p = tid >> 3, nb = tid & 7;

    float q1 = (c == 2) ? g_pref[(size_t)bh * LSEQ + 2 * LCH - 1] : 0.f;
    ull sini[8];
    {
        const float4* s1 = (const float4*)(g_cstate + ((size_t)bh * 2 + (c - 1)) * 8192
                                           + p * 128 + nb * 16);
        const float4* s0 = (const float4*)(g_cstate + ((size_t)bh * 2) * 8192
                                           + p * 128 + nb * 16);
#pragma unroll
        for (int i = 0; i < 4; i++) {
            float4 v = s1[i];
            if (c == 2) {
                float4 w = s0[i];
                v.x = fmaf(q1, w.x, v.x); v.y = fmaf(q1, w.y, v.y);
                v.z = fmaf(q1, w.z, v.z); v.w = fmaf(q1, w.w, v.w);
            }
            sini[2*i]   = pk2(v.x, v.y);
            sini[2*i+1] = pk2(v.z, v.w);
        }
    }

    const char* src = nullptr;
    uint32_t dsto = 0;
    size_t stride = (size_t)CONVD * 4;
    if (tid < 32) {
        src = (const char*)(g_xc + ((size_t)b * LSEQ + t0) * CONVD + DINNER + DST) + tid * 16;
        dsto = (uint32_t)((((tid & 3) * 8) + (tid >> 2)) * 16);
    } else if (tid == 32) {
        src = (const char*)(g_pref + (size_t)bh * LSEQ + t0);
        dsto = 512;
        stride = 4;
    }

    auto issue_group = [&](int gq) {
#pragma unroll
        for (int q = 0; q < 4; q++) {
            int step = 4 * gq + q;
            if (step < Th && tid <= 32) {
                uint32_t d = sb + (uint32_t)((step & (FSTG - 1)) * (FSTGF * 4)) + dsto;
                if (tid < 32) cp16(d, src); else cp4(d, src);
                src += stride;
            }
        }
        cp_commit();
    };
    issue_group(0); issue_group(1); issue_group(2);

    float* ybase = g_y + ((size_t)b * LSEQ + t0) * DINNER + h * HD;
    int rs = tid >> 6, rp = tid & 63;

    for (int g = 0; g < Th / 4; g++) {
        cp_wait2();
        __syncthreads();
        issue_group(g + 3);

#pragma unroll
        for (int q = 0; q < 4; q++) {
            int l = 4 * g + q;
            const float* bp = sh[l & (FSTG - 1)];
            const ulonglong2* C4 = (const ulonglong2*)bp;
            ull cc[8];
#pragma unroll
            for (int j = 0; j < 4; j++) {
                ulonglong2 cv = C4[j * 8 + nb];
                cc[2*j] = cv.x; cc[2*j+1] = cv.y;
            }
            ull acc2 = 0ull;
#pragma unroll
            for (int i = 0; i < 8; i++) acc2 = f2fma(sini[i], cc[i], acc2);
            float2 av = upk2(acc2);
            yb[l & 7][tid] = (av.x + av.y) * bp[128];
        }

        if (g & 1) {
            __syncthreads();
            const float4* r4 = (const float4*)(yb[rs] + rp * 8);
            float4 v0 = r4[0], v1 = r4[1];
            float acc = ((v0.x + v0.y) + (v0.z + v0.w))
                      + ((v1.x + v1.y) + (v1.z + v1.w));
            int l0 = 4 * (g - 1);
            float* yp = ybase + (size_t)(l0 + rs) * DINNER + rp;
            *yp += acc;
        }
    }
}

// ---------------------------------------------------------------------------
// gate + rmsnorm, now includes D skip: v = (y + D*x) * silu(z)
// ---------------------------------------------------------------------------
__global__ __launch_bounds__(384)
void gate_norm(const float* __restrict__ nw, const float* __restrict__ Dv)
{
    __shared__ float warpsum[12];
    __shared__ float stot;
    int m = blockIdx.x;
    int tid = threadIdx.x;
    float Dh = Dv[tid >> 4];                  // head = 4*tid/64
    float4 yv = ((const float4*)(g_y + (size_t)m * DINNER))[tid];
    float4 xv = ((const float4*)(g_xc + (size_t)m * CONVD))[tid];
    float4 zv = ((const float4*)(g_zx + (size_t)m * NPROJ))[tid];
    yv.x = fmaf(Dh, xv.x, yv.x);
    yv.y = fmaf(Dh, xv.y, yv.y);
    yv.z = fmaf(Dh, xv.z, yv.z);
    yv.w = fmaf(Dh, xv.w, yv.w);
    float4 v;
    v.x = yv.x * (zv.x / (1.f + __expf(-zv.x)));
    v.y = yv.y * (zv.y / (1.f + __expf(-zv.y)));
    v.z = yv.z * (zv.z / (1.f + __expf(-zv.z)));
    v.w = yv.w * (zv.w / (1.f + __expf(-zv.w)));
    float ss = fmaf(v.x, v.x, fmaf(v.y, v.y, fmaf(v.z, v.z, v.w * v.w)));
#pragma unroll
    for (int o = 16; o > 0; o >>= 1) ss += __shfl_xor_sync(0xffffffffu, ss, o);
    if ((tid & 31) == 0) warpsum[tid >> 5] = ss;
    __syncthreads();
    if (tid == 0) {
        float t = 0.f;
#pragma unroll
        for (int w = 0; w < 12; w++) t += warpsum[w];
        stot = t;
    }
    __syncthreads();
    float scale = rsqrtf(stot / (float)DINNER + 1e-5f);
    float4 nv = ((const float4*)nw)[tid];
    v.x *= scale * nv.x; v.y *= scale * nv.y;
    v.z *= scale * nv.z; v.w *= scale * nv.w;
    __half2 h0 = __floats2half2_rn(v.x, v.y);
    __half2 h1 = __floats2half2_rn(v.z, v.w);
    ((uint2*)(g_Yh + (size_t)m * DINNER))[tid] =
        make_uint2(*(uint32_t*)&h0, *(uint32_t*)&h1);
}

// ---------------------------------------------------------------------------
extern "C" void kernel_launch(void* const* d_in, const int* in_sizes, int n_in,
                              void* d_out, int out_size)
{
    const float* x    = (const float*)d_in[0];
    const float* wi   = (const float*)d_in[1];
    const float* cw   = (const float*)d_in[2];
    const float* cb   = (const float*)d_in[3];
    const float* dtb  = (const float*)d_in[4];
    const float* alog = (const float*)d_in[5];
    const float* Dv   = (const float*)d_in[6];
    const float* nw   = (const float*)d_in[7];
    const float* wo   = (const float*)d_in[8];
    float* out = (float*)d_out;

    float *zx;
    __half *xh, *wih, *yh, *woh;
    cudaGetSymbolAddress((void**)&zx,  g_zx);
    cudaGetSymbolAddress((void**)&xh,  g_Xh);
    cudaGetSymbolAddress((void**)&wih, g_Wih);
    cudaGetSymbolAddress((void**)&yh,  g_Yh);
    cudaGetSymbolAddress((void**)&woh, g_Woh);

    static const int smem_bytes = 2 * STAGE_B;  // 110592 B
    cudaFuncSetAttribute(mma_gemm, cudaFuncAttributeMaxDynamicSharedMemorySize, smem_bytes);

    dim3 blk(256);

    conv_hi16<<<(M_TOK * DMODEL / 4 + 255) / 256, blk>>>(x, xh,
                                                         M_TOK * DMODEL / 4, M_TOK * DMODEL / 4);
    conv_hi16<<<(NPAD * DMODEL / 4 + 255) / 256, blk>>>(wi, wih,
                                                        NPROJ * DMODEL / 4, NPAD * DMODEL / 4);
    conv_hi16<<<(DMODEL * DINNER / 4 + 255) / 256, blk>>>(wo, woh,
                                                          DMODEL * DINNER / 4, DMODEL * DINNER / 4);

    mma_gemm<<<dim3(NPAD / 128, M_TOK / 256), blk, smem_bytes>>>(
        xh, wih, nullptr, zx, NPROJ, DMODEL);

    dt_exact<<<M_TOK / DTB, blk>>>(x, wi, dtb, alog);
    conv_silu<<<((M_TOK / 4) * (CONVD / 4) + 255) / 256, blk>>>(cw, cb);
    scan_kernel<<<288, 256>>>();
    fixup_kernel<<<384, 512>>>();
    gate_norm<<<M_TOK, 384>>>(nw, Dv);

    mma_gemm<<<dim3(DMODEL / 128, M_TOK / 256), blk, smem_bytes>>>(
        yh, woh, x, out, DMODEL, DINNER);
}

// round 16
// speedup vs baseline: 1.0865x; 1.0224x over previous
#include <cuda_runtime.h>
#include <cuda_fp16.h>
#include <cstdint>

#define M_TOK 8192
#define DMODEL 768
#define DINNER 1536
#define CONVD  1792
#define NH     24
#define HD     64
#define DST    128
#define NPROJ  3352
#define NPAD   3456
#define LSEQ   2048

// ---------------- device scratch (no allocation allowed) ----------------
__device__ float g_zx[M_TOK * NPROJ];    // in_proj output (z | xBC | dt-unused)
__device__ float g_xc[M_TOK * CONVD];    // conv+silu output (xh | B | C)
__device__ float2 g_dtdA[96 * LSEQ];     // packed (dt, dA) per (b*NH+h, l)
__device__ float g_y [M_TOK * DINNER];   // scan output (no D skip; added in gate_norm)
__device__ float g_cstate[96 * 2 * 64 * 128];  // per-chunk final local state
__device__ float g_pref[96 * LSEQ];            // per-chunk dA prefix products

__device__ __half g_Xh[M_TOK * DMODEL];
__device__ __half g_Wih[NPAD * DMODEL];
__device__ __half g_Yh[M_TOK * DINNER];
__device__ __half g_Woh[DMODEL * DINNER];

typedef unsigned long long ull;

__device__ __forceinline__ uint32_t smem_u32(const void* p) {
    uint32_t a;
    asm("{ .reg .u64 t; cvta.to.shared.u64 t, %1; cvt.u32.u64 %0, t; }"
        : "=r"(a) : "l"(p));
    return a;
}

__device__ __forceinline__ void cp16(uint32_t dst, const void* src) {
    asm volatile("cp.async.cg.shared.global [%0], [%1], 16;"
                 :: "r"(dst), "l"(src) : "memory");
}
__device__ __forceinline__ void cp8(uint32_t dst, const void* src) {
    asm volatile("cp.async.ca.shared.global [%0], [%1], 8;"
                 :: "r"(dst), "l"(src) : "memory");
}
__device__ __forceinline__ void cp4(uint32_t dst, const void* src) {
    asm volatile("cp.async.ca.shared.global [%0], [%1], 4;"
                 :: "r"(dst), "l"(src) : "memory");
}
__device__ __forceinline__ void cp_commit() {
    asm volatile("cp.async.commit_group;" ::: "memory");
}
__device__ __forceinline__ void cp_wait0() {
    asm volatile("cp.async.wait_group 0;" ::: "memory");
}
__device__ __forceinline__ void cp_wait1() {
    asm volatile("cp.async.wait_group 1;" ::: "memory");
}
__device__ __forceinline__ void cp_wait2() {
    asm volatile("cp.async.wait_group 2;" ::: "memory");
}

__device__ __forceinline__ void ldmx4(uint32_t* r, uint32_t addr) {
    asm volatile("ldmatrix.sync.aligned.m8n8.x4.shared.b16 {%0,%1,%2,%3}, [%4];"
                 : "=r"(r[0]), "=r"(r[1]), "=r"(r[2]), "=r"(r[3]) : "r"(addr));
}

__device__ __forceinline__ void mma16816h(float* c, const uint32_t* a, const uint32_t* b) {
    asm volatile(
        "mma.sync.aligned.m16n8k16.row.col.f32.f16.f16.f32 "
        "{%0,%1,%2,%3}, {%4,%5,%6,%7}, {%8,%9}, {%0,%1,%2,%3};"
        : "+f"(c[0]), "+f"(c[1]), "+f"(c[2]), "+f"(c[3])
        : "r"(a[0]), "r"(a[1]), "r"(a[2]), "r"(a[3]), "r"(b[0]), "r"(b[1]));
}

// ---------------------------------------------------------------------------
// fp16 1-pass GEMM (NT): C = fp16(A) * fp16(B)^T, fp32 accumulate.
// CTA tile 256x128, 8 warps (warp tile 64x64), K-chunk 64, 2-stage ring.
// ---------------------------------------------------------------------------
#define BK      64
#define LDT_B   144
#define ROW_A   256
#define ROW_BT  128
#define STAGE_B ((ROW_A + ROW_BT) * LDT_B)   // 55296

__global__ __launch_bounds__(256, 1)
void mma_gemm(const __half* __restrict__ Ah_, const __half* __restrict__ Bh_,
              const float* __restrict__ R, float* __restrict__ C,
              int Nact, int K)
{
    extern __shared__ char smem[];
    uint32_t sb = smem_u32(smem);
    int tid  = threadIdx.x;
    int wid  = tid >> 5, lane = tid & 31;
    int wm   = wid & 3, wn = wid >> 2;
    int m0   = blockIdx.y * 256, n0 = blockIdx.x * 128;

    const size_t rowK = (size_t)K * 2;

    auto load_stage = [&](int s, int k0) {
        uint32_t d0 = sb + s * STAGE_B;
#pragma unroll
        for (int i = 0; i < 12; i++) {
            int idx = tid + i * 256;
            int row = idx >> 3, ch = idx & 7;
            const char* src;
            if (row < ROW_A)
                src = (const char*)Ah_ + (size_t)(m0 + row) * rowK + k0 * 2;
            else
                src = (const char*)Bh_ + (size_t)(n0 + row - ROW_A) * rowK + k0 * 2;
            cp16(d0 + row * LDT_B + ch * 16, src + ch * 16);
        }
        cp_commit();
    };

    float acc[4][8][4];
#pragma unroll
    for (int mt = 0; mt < 4; mt++)
#pragma unroll
        for (int nt = 0; nt < 8; nt++)
#pragma unroll
            for (int j = 0; j < 4; j++) acc[mt][nt][j] = 0.f;

    int nch = K / BK;
    load_stage(0, 0);

    int a_row = wm * 64 + (lane & 7) + ((lane >> 3) & 1) * 8;
    int a_cb  = ((lane >> 4) & 1) * 16;
    int b_row = wn * 64 + ((lane >> 4) & 1) * 8 + (lane & 7);
    int b_cb  = ((lane >> 3) & 1) * 16;

    for (int c = 0; c < nch; c++) {
        if (c + 1 < nch) { load_stage((c + 1) & 1, (c + 1) * BK); cp_wait1(); }
        else             { cp_wait0(); }
        __syncthreads();

        uint32_t st = sb + (c & 1) * STAGE_B;
        uint32_t Ah = st;
        uint32_t Bh = st + ROW_A * LDT_B;

#pragma unroll
        for (int kk = 0; kk < 4; kk++) {
            int kb = kk * 32;
            uint32_t ah[4][4];
#pragma unroll
            for (int mt = 0; mt < 4; mt++) {
                uint32_t off = (uint32_t)((a_row + mt * 16) * LDT_B + kb + a_cb);
                ldmx4(ah[mt], Ah + off);
            }
            uint32_t bh[8][2];
#pragma unroll
            for (int q = 0; q < 4; q++) {
                uint32_t off = (uint32_t)((b_row + q * 16) * LDT_B + kb + b_cb);
                uint32_t r[4];
                ldmx4(r, Bh + off);
                bh[2*q][0] = r[0]; bh[2*q][1] = r[1];
                bh[2*q+1][0] = r[2]; bh[2*q+1][1] = r[3];
            }
#pragma unroll
            for (int mt = 0; mt < 4; mt++)
#pragma unroll
                for (int nt = 0; nt < 8; nt++)
                    mma16816h(acc[mt][nt], ah[mt], bh[nt]);
        }
        __syncthreads();
    }

    int l4 = lane >> 2, l2 = (lane & 3) * 2;
#pragma unroll
    for (int mt = 0; mt < 4; mt++) {
        int gm = m0 + wm * 64 + mt * 16 + l4;
#pragma unroll
        for (int nt = 0; nt < 8; nt++) {
            int gn = n0 + wn * 64 + nt * 8 + l2;
            if (gn < Nact) {
                size_t o0 = (size_t)gm * Nact + gn;
                size_t o1 = (size_t)(gm + 8) * Nact + gn;
                float2 v0 = make_float2(acc[mt][nt][0], acc[mt][nt][1]);
                float2 v1 = make_float2(acc[mt][nt][2], acc[mt][nt][3]);
                if (R) {
                    const float2 r0 = *(const float2*)&R[o0];
                    const float2 r1 = *(const float2*)&R[o1];
                    v0.x += r0.x; v0.y += r0.y; v1.x += r1.x; v1.y += r1.y;
                }
                *(float2*)&C[o0] = v0;
                *(float2*)&C[o1] = v1;
            }
        }
    }
}

// ---------------------------------------------------------------------------
// fp32 -> fp16 convert (float4-vectorized, zero-padded)
// ---------------------------------------------------------------------------
__global__ void conv_hi16(const float* __restrict__ w, __half* __restrict__ hi,
                          int nsrc4, int ntot4)
{
    int i = blockIdx.x * blockDim.x + threadIdx.x;
    if (i >= ntot4) return;
    float4 v = make_float4(0.f, 0.f, 0.f, 0.f);
    if (i < nsrc4) v = ((const float4*)w)[i];
    __half2 h0 = __floats2half2_rn(v.x, v.y);
    __half2 h1 = __floats2half2_rn(v.z, v.w);
    ((uint2*)hi)[i] = make_uint2(*(uint32_t*)&h0, *(uint32_t*)&h1);
}

// ---------------------------------------------------------------------------
__device__ __forceinline__ ull pk2(float x, float y) {
    ull r; asm("mov.b64 %0,{%1,%2};" : "=l"(r) : "f"(x), "f"(y)); return r;
}
__device__ __forceinline__ float2 upk2(ull v) {
    float2 r; asm("mov.b64 {%0,%1},%2;" : "=f"(r.x), "=f"(r.y) : "l"(v)); return r;
}
__device__ __forceinline__ ull f2fma(ull a, ull b, ull c) {
    ull d; asm("fma.rn.f32x2 %0,%1,%2,%3;" : "=l"(d) : "l"(a), "l"(b), "l"(c)); return d;
}
__device__ __forceinline__ ull f2mul(ull a, ull b) {
    ull d; asm("mul.rn.f32x2 %0,%1,%2;" : "=l"(d) : "l"(a), "l"(b)); return d;
}

// ---------------------------------------------------------------------------
// Causal depthwise conv1d + SiLU: 4 timesteps x 4 channels per thread.
// ---------------------------------------------------------------------------
__global__ void conv_silu(const float* __restrict__ cw, const float* __restrict__ cb)
{
    int idx = blockIdx.x * blockDim.x + threadIdx.x;
    if (idx >= (M_TOK / 4) * (CONVD / 4)) return;
    int c4 = idx % (CONVD / 4), mg = idx / (CONVD / 4);
    int c = c4 * 4;
    int m0 = mg * 4;
    int l0 = m0 & (LSEQ - 1);

    float4 w0 = ((const float4*)cw)[c];
    float4 w1 = ((const float4*)cw)[c + 1];
    float4 w2 = ((const float4*)cw)[c + 2];
    float4 w3 = ((const float4*)cw)[c + 3];
    const float* wk0 = (const float*)&w0;
    const float* wk1 = (const float*)&w1;
    const float* wk2 = (const float*)&w2;
    const float* wk3 = (const float*)&w3;
    float4 bias = *(const float4*)&cb[c];

    float4 tap[7];
#pragma unroll
    for (int j = 0; j < 7; j++) {
        int l = l0 - 3 + j;
        tap[j] = (l >= 0) ? *(const float4*)&g_zx[(size_t)(m0 - 3 + j) * NPROJ + DINNER + c]
                          : make_float4(0.f, 0.f, 0.f, 0.f);
    }

#pragma unroll
    for (int t = 0; t < 4; t++) {
        float4 acc = bias;
#pragma unroll
        for (int k = 0; k < 4; k++) {
            float4 xv = tap[t + k];
            acc.x = fmaf(xv.x, wk0[k], acc.x);
            acc.y = fmaf(xv.y, wk1[k], acc.y);
            acc.z = fmaf(xv.z, wk2[k], acc.z);
            acc.w = fmaf(xv.w, wk3[k], acc.w);
        }
        acc.x *= 1.f / (1.f + __expf(-acc.x));
        acc.y *= 1.f / (1.f + __expf(-acc.y));
        acc.z *= 1.f / (1.f + __expf(-acc.z));
        acc.w *= 1.f / (1.f + __expf(-acc.w));
        *(float4*)&g_xc[(size_t)(m0 + t) * CONVD + c] = acc;
    }
}

// ---------------------------------------------------------------------------
// EXACT fp32 dt path, 16 tokens per CTA.
// ---------------------------------------------------------------------------
#define DTB 16

__global__ __launch_bounds__(256)
void dt_exact(const float* __restrict__ x, const float* __restrict__ wi,
              const float* __restrict__ dtb, const float* __restrict__ alog)
{
    __shared__ __align__(16) float xrow[DTB][DMODEL];   // 48 KB
    int m0 = blockIdx.x * DTB;
    int tid = threadIdx.x;
    for (int i = tid; i < DTB * DMODEL / 4; i += 256)
        ((float4*)xrow)[i] = ((const float4*)(x + (size_t)m0 * DMODEL))[i];
    __syncthreads();

    int w = tid >> 5, lane = tid & 31;
#pragma unroll
    for (int hh = 0; hh < 3; hh++) {
        int h = w + hh * 8;
        float A = -expf(alog[h]);
        float db = dtb[h];
        const float4* wr4 = (const float4*)(wi + (size_t)(DINNER + CONVD + h) * DMODEL);
        float4 wreg[6];
#pragma unroll
        for (int j = 0; j < 6; j++) wreg[j] = wr4[lane + j * 32];

        for (int t = 0; t < DTB; t++) {
            const float4* xr4 = (const float4*)xrow[t];
            float dot = 0.f;
#pragma unroll
            for (int j = 0; j < 6; j++) {
                float4 a = xr4[lane + j * 32];
                float4 b = wreg[j];
                dot = fmaf(a.x, b.x, fmaf(a.y, b.y, fmaf(a.z, b.z, fmaf(a.w, b.w, dot))));
            }
#pragma unroll
            for (int o = 16; o > 0; o >>= 1) dot += __shfl_xor_sync(0xffffffffu, dot, o);
            if (lane == 0) {
                int m = m0 + t;
                float v = dot + db;
                float sp = fmaxf(v, 0.f) + log1pf(expf(-fabsf(v)));
                int b = m / LSEQ, l = m % LSEQ;
                g_dtdA[(size_t)(b * NH + h) * LSEQ + l] = make_float2(sp, expf(sp * A));
            }
        }
    }
}

// ---------------------------------------------------------------------------
// Chunked selective SSM scan (3 chunks, 2 CTAs/SM). 32-stage ring,
// 8 steps per commit group, 2 barriers per 8 steps (was 3 + 2 waits).
// ---------------------------------------------------------------------------
#define NSTG 32
#define STGF 336
#define LCH  688

__global__ __launch_bounds__(256, 2)
void scan_kernel()
{
    __shared__ __align__(16) float sh[NSTG][STGF];     // 43008 B
    __shared__ __align__(16) float yb[8][1024];        // 32768 B
    uint32_t sb = smem_u32(sh);
    int bc = blockIdx.x;
    int bh = bc % 96;
    int c  = bc / 96;
    int t0 = c * LCH;
    int T  = (c < 2) ? LCH : (LSEQ - 2 * LCH);         // 688 / 688 / 672 (all %8==0)
    int b = bh / NH, h = bh % NH;
    int tid = threadIdx.x;
    int pg = tid >> 4, nq = tid & 15;
    int xorm = (pg & 1) * 16;

    const char* src = nullptr;
    uint32_t dsto = 0;
    size_t stride = (size_t)CONVD * 4;
    const char* xcb = (const char*)(g_xc + ((size_t)b * LSEQ + t0) * CONVD);
    if (tid < 16) {
        src = xcb + (size_t)h * HD * 4 + tid * 16;
        dsto = tid * 16;
    } else if (tid < 48) {
        int t = tid - 16;
        src = xcb + (size_t)DINNER * 4 + t * 16;
        dsto = 256 + (uint32_t)((((t & 1) * 16) + (t >> 1)) * 16);
    } else if (tid < 80) {
        int t = tid - 48;
        src = xcb + (size_t)(DINNER + DST) * 4 + t * 16;
        dsto = 768 + (uint32_t)((((t & 1) * 16) + (t >> 1)) * 16);
    } else if (tid == 80) {
        src = (const char*)(g_dtdA + (size_t)bh * LSEQ + t0);
        dsto = 1280;
        stride = 8;
    }

    // 8 steps per commit group
    auto issue_group = [&](int gq) {
#pragma unroll
        for (int q = 0; q < 8; q++) {
            int step = 8 * gq + q;
            if (step < T && tid <= 80) {
                uint32_t d = sb + (uint32_t)((step & (NSTG - 1)) * (STGF * 4)) + dsto;
                if (tid < 80) cp16(d, src); else cp8(d, src);
                src += stride;
            }
        }
        cp_commit();
    };

    issue_group(0); issue_group(1); issue_group(2);    // stages 0..23

    ull st[4][4];
#pragma unroll
    for (int pi = 0; pi < 4; pi++)
#pragma unroll
        for (int k = 0; k < 4; k++) st[pi][k] = 0ull;

    float* ybase = g_y + ((size_t)b * LSEQ + t0) * DINNER + h * HD;
    float run = 1.f;
    float* prefp = g_pref + (size_t)bh * LSEQ + t0;

    for (int g = 0; g < T / 8; g++) {
        cp_wait2();            // group g complete (3 in flight -> 2)
        __syncthreads();       // data visible; prev reduce finished (yb free)
        issue_group(g + 3);    // overwrites stages of group g-1 (consumed)

#pragma unroll 2
        for (int q2 = 0; q2 < 2; q2++) {
#pragma unroll
            for (int q = 0; q < 4; q++) {
                int l = 8 * g + q2 * 4 + q;
                const float* bp = sh[l & (NSTG - 1)];
                float4 xv = *(const float4*)(bp + 4 * pg);
                float2 da = *(const float2*)(bp + 320);
                ull dA2 = pk2(da.y, da.y);
                float xs[4] = {xv.x, xv.y, xv.z, xv.w};
                ull dtx2[4];
#pragma unroll
                for (int pi = 0; pi < 4; pi++) {
                    float d = da.x * xs[pi];
                    dtx2[pi] = pk2(d, d);
                }
                const ulonglong2* B4 = (const ulonglong2*)(bp + 64);
                const ulonglong2* C4 = (const ulonglong2*)(bp + 192);
                ull bb[4], cc[4];
#pragma unroll
                for (int j = 0; j < 2; j++) {
                    ulonglong2 bv = B4[j * 16 + nq];
                    ulonglong2 cv = C4[j * 16 + nq];
                    bb[2*j] = bv.x; bb[2*j+1] = bv.y;
                    cc[2*j] = cv.x; cc[2*j+1] = cv.y;
                }
                float* yrow = yb[l & 7] + 64 * pg;
#pragma unroll
                for (int pi = 0; pi < 4; pi++) {
                    ull acc2 = 0ull;
#pragma unroll
                    for (int k = 0; k < 4; k++) {
                        st[pi][k] = f2fma(st[pi][k], dA2, f2mul(dtx2[pi], bb[k]));
                        acc2 = f2fma(st[pi][k], cc[k], acc2);
                    }
                    float2 av = upk2(acc2);
                    yrow[(16 * pi + nq) ^ xorm] = av.x + av.y;
                }
                if (tid == 255 && c > 0) {
                    run *= da.y;
                    prefp[l] = run;
                }
            }
        }

        __syncthreads();       // all 8 steps' partials written
#pragma unroll
        for (int k = 0; k < 2; k++) {
            int o = tid + 256 * k;
            int s_ = o >> 6, p = o & 63;
            int rpg = p >> 2, rpi = p & 3;
            const float4* r4 = (const float4*)(yb[s_] + 64 * rpg
                                               + (16 * (rpi ^ (rpg & 1))));
            float4 v0 = r4[0], v1 = r4[1], v2 = r4[2], v3 = r4[3];
            float acc = (((v0.x + v0.y) + (v0.z + v0.w))
                       + ((v1.x + v1.y) + (v1.z + v1.w)))
                      + (((v2.x + v2.y) + (v2.z + v2.w))
                       + ((v3.x + v3.y) + (v3.z + v3.w)));
            int l0 = 8 * g;
            ybase[(size_t)(l0 + s_) * DINNER + p] = acc;
        }
    }

    if (c < 2) {
        float* cs = g_cstate + ((size_t)bh * 2 + c) * 8192;
#pragma unroll
        for (int pi = 0; pi < 4; pi++) {
            int p = 4 * pg + pi;
#pragma unroll
            for (int j = 0; j < 2; j++) {
                float2 a = upk2(st[pi][2*j]);
                float2 d = upk2(st[pi][2*j+1]);
                float4 v = make_float4(a.x, a.y, d.x, d.y);
                *(float4*)(cs + p * 128 + 8 * nq + 4 * j) = v;
            }
        }
    }
}

// ---------------------------------------------------------------------------
// Fix-up (unchanged).
// ---------------------------------------------------------------------------
#define FSTG 16
#define FSTGF 132

__global__ __launch_bounds__(512, 2)
void fixup_kernel()
{
    __shared__ __align__(16) float sh[FSTG][FSTGF];
    __shared__ __align__(16) float yb[8][512];
    uint32_t sb = smem_u32(sh);
    int bx = blockIdx.x;
    int bh = bx % 96;
    int r  = bx / 96;
    int c  = 1 + (r >> 1);
    int half = r & 1;
    int Tc = (c == 1) ? LCH : (LSEQ - 2 * LCH);
    int Th = Tc / 2;
    int t0 = c * LCH + half * Th;
    int b = bh / NH, h = bh % NH;
    int tid = threadIdx.x;
    int p = tid >> 3, nb = tid & 7;

    float q1 = (c == 2) ? g_pref[(size_t)bh * LSEQ + 2 * LCH - 1] : 0.f;
    ull sini[8];
    {
        const float4* s1 = (const float4*)(g_cstate + ((size_t)bh * 2 + (c - 1)) * 8192
                                           + p * 128 + nb * 16);
        const float4* s0 = (const float4*)(g_cstate + ((size_t)bh * 2) * 8192
                                           + p * 128 + nb * 16);
#pragma unroll
        for (int i = 0; i < 4; i++) {
            float4 v = s1[i];
            if (c == 2) {
                float4 w = s0[i];
                v.x = fmaf(q1, w.x, v.x); v.y = fmaf(q1, w.y, v.y);
                v.z = fmaf(q1, w.z, v.z); v.w = fmaf(q1, w.w, v.w);
            }
            sini[2*i]   = pk2(v.x, v.y);
            sini[2*i+1] = pk2(v.z, v.w);
        }
    }

    const char* src = nullptr;
    uint32_t dsto = 0;
    size_t stride = (size_t)CONVD * 4;
    if (tid < 32) {
        src = (const char*)(g_xc + ((size_t)b * LSEQ + t0) * CONVD + DINNER + DST) + tid * 16;
        dsto = (uint32_t)((((tid & 3) * 8) + (tid >> 2)) * 16);
    } else if (tid == 32) {
        src = (const char*)(g_pref + (size_t)bh * LSEQ + t0);
        dsto = 512;
        stride = 4;
    }

    auto issue_group = [&](int gq) {
#pragma unroll
        for (int q = 0; q < 4; q++) {
            int step = 4 * gq + q;
            if (step < Th && tid <= 32) {
                uint32_t d = sb + (uint32_t)((step & (FSTG - 1)) * (FSTGF * 4)) + dsto;
                if (tid < 32) cp16(d, src); else cp4(d, src);
                src += stride;
            }
        }
        cp_commit();
    };
    issue_group(0); issue_group(1); issue_group(2);

    float* ybase = g_y + ((size_t)b * LSEQ + t0) * DINNER + h * HD;
    int rs = tid >> 6, rp = tid & 63;

    for (int g = 0; g < Th / 4; g++) {
        cp_wait2();
        __syncthreads();
        issue_group(g + 3);

#pragma unroll
        for (int q = 0; q < 4; q++) {
            int l = 4 * g + q;
            const float* bp = sh[l & (FSTG - 1)];
            const ulonglong2* C4 = (const ulonglong2*)bp;
            ull cc[8];
#pragma unroll
            for (int j = 0; j < 4; j++) {
                ulonglong2 cv = C4[j * 8 + nb];
                cc[2*j] = cv.x; cc[2*j+1] = cv.y;
            }
            ull acc2 = 0ull;
#pragma unroll
            for (int i = 0; i < 8; i++) acc2 = f2fma(sini[i], cc[i], acc2);
            float2 av = upk2(acc2);
            yb[l & 7][tid] = (av.x + av.y) * bp[128];
        }

        if (g & 1) {
            __syncthreads();
            const float4* r4 = (const float4*)(yb[rs] + rp * 8);
            float4 v0 = r4[0], v1 = r4[1];
            float acc = ((v0.x + v0.y) + (v0.z + v0.w))
                      + ((v1.x + v1.y) + (v1.z + v1.w));
            int l0 = 4 * (g - 1);
            float* yp = ybase + (size_t)(l0 + rs) * DINNER + rp;
            *yp += acc;
        }
    }
}

// ---------------------------------------------------------------------------
// gate + rmsnorm with D skip: v = (y + D*x) * silu(z)
// ---------------------------------------------------------------------------
__global__ __launch_bounds__(384)
void gate_norm(const float* __restrict__ nw, const float* __restrict__ Dv)
{
    __shared__ float warpsum[12];
    __shared__ float stot;
    int m = blockIdx.x;
    int tid = threadIdx.x;
    float Dh = Dv[tid >> 4];
    float4 yv = ((const float4*)(g_y + (size_t)m * DINNER))[tid];
    float4 xv = ((const float4*)(g_xc + (size_t)m * CONVD))[tid];
    float4 zv = ((const float4*)(g_zx + (size_t)m * NPROJ))[tid];
    yv.x = fmaf(Dh, xv.x, yv.x);
    yv.y = fmaf(Dh, xv.y, yv.y);
    yv.z = fmaf(Dh, xv.z, yv.z);
    yv.w = fmaf(Dh, xv.w, yv.w);
    float4 v;
    v.x = yv.x * (zv.x / (1.f + __expf(-zv.x)));
    v.y = yv.y * (zv.y / (1.f + __expf(-zv.y)));
    v.z = yv.z * (zv.z / (1.f + __expf(-zv.z)));
    v.w = yv.w * (zv.w / (1.f + __expf(-zv.w)));
    float ss = fmaf(v.x, v.x, fmaf(v.y, v.y, fmaf(v.z, v.z, v.w * v.w)));
#pragma unroll
    for (int o = 16; o > 0; o >>= 1) ss += __shfl_xor_sync(0xffffffffu, ss, o);
    if ((tid & 31) == 0) warpsum[tid >> 5] = ss;
    __syncthreads();
    if (tid == 0) {
        float t = 0.f;
#pragma unroll
        for (int w = 0; w < 12; w++) t += warpsum[w];
        stot = t;
    }
    __syncthreads();
    float scale = rsqrtf(stot / (float)DINNER + 1e-5f);
    float4 nv = ((const float4*)nw)[tid];
    v.x *= scale * nv.x; v.y *= scale * nv.y;
    v.z *= scale * nv.z; v.w *= scale * nv.w;
    __half2 h0 = __floats2half2_rn(v.x, v.y);
    __half2 h1 = __floats2half2_rn(v.z, v.w);
    ((uint2*)(g_Yh + (size_t)m * DINNER))[tid] =
        make_uint2(*(uint32_t*)&h0, *(uint32_t*)&h1);
}

// ---------------------------------------------------------------------------
extern "C" void kernel_launch(void* const* d_in, const int* in_sizes, int n_in,
                              void* d_out, int out_size)
{
    const float* x    = (const float*)d_in[0];
    const float* wi   = (const float*)d_in[1];
    const float* cw   = (const float*)d_in[2];
    const float* cb   = (const float*)d_in[3];
    const float* dtb  = (const float*)d_in[4];
    const float* alog = (const float*)d_in[5];
    const float* Dv   = (const float*)d_in[6];
    const float* nw   = (const float*)d_in[7];
    const float* wo   = (const float*)d_in[8];
    float* out = (float*)d_out;

    float *zx;
    __half *xh, *wih, *yh, *woh;
    cudaGetSymbolAddress((void**)&zx,  g_zx);
    cudaGetSymbolAddress((void**)&xh,  g_Xh);
    cudaGetSymbolAddress((void**)&wih, g_Wih);
    cudaGetSymbolAddress((void**)&yh,  g_Yh);
    cudaGetSymbolAddress((void**)&woh, g_Woh);

    static const int smem_bytes = 2 * STAGE_B;  // 110592 B
    cudaFuncSetAttribute(mma_gemm, cudaFuncAttributeMaxDynamicSharedMemorySize, smem_bytes);

    dim3 blk(256);

    conv_hi16<<<(M_TOK * DMODEL / 4 + 255) / 256, blk>>>(x, xh,
                                                         M_TOK * DMODEL / 4, M_TOK * DMODEL / 4);
    conv_hi16<<<(NPAD * DMODEL / 4 + 255) / 256, blk>>>(wi, wih,
                                                        NPROJ * DMODEL / 4, NPAD * DMODEL / 4);
    conv_hi16<<<(DMODEL * DINNER / 4 + 255) / 256, blk>>>(wo, woh,
                                                          DMODEL * DINNER / 4, DMODEL * DINNER / 4);

    mma_gemm<<<dim3(NPAD / 128, M_TOK / 256), blk, smem_bytes>>>(
        xh, wih, nullptr, zx, NPROJ, DMODEL);

    dt_exact<<<M_TOK / DTB, blk>>>(x, wi, dtb, alog);
    conv_silu<<<((M_TOK / 4) * (CONVD / 4) + 255) / 256, blk>>>(cw, cb);
    scan_kernel<<<288, 256>>>();
    fixup_kernel<<<384, 512>>>();
    gate_norm<<<M_TOK, 384>>>(nw, Dv);

    mma_gemm<<<dim3(DMODEL / 128, M_TOK / 256), blk, smem_bytes>>>(
        yh, woh, x, out, DMODEL, DINNER);
}